// round 15
// baseline (speedup 1.0000x reference)
#include <cuda_runtime.h>
#include <cuda_bf16.h>
#include <cstdint>

#define NMAX 32768
#define EMAX 262144

// Scratch
__device__ float g_h   [NMAX * 128];
__device__ float g_aggH[NMAX * 256];
__device__ float g_flat[2 * 256 * 64 * 128];   // layout: pair*128 + (q | 64+c)
__device__ float g_P   [NMAX * 512];
__device__ float g_wc  [256 * 128];
__device__ float g_bc  [128];
__device__ float g_wpe [16 * 256];
__device__ float g_bpe [256];
__device__ int   g_deg [NMAX];
__device__ __align__(16) __nv_bfloat16 g_h_hi[NMAX * 128];
__device__ __align__(16) __nv_bfloat16 g_h_lo[NMAX * 128];
__device__ __align__(16) __nv_bfloat16 g_w1p_hi[512 * 128], g_w1p_lo[512 * 128];
__device__ __align__(16) __nv_bfloat16 g_wut2_hi[128 * 384], g_wut2_lo[128 * 384];
__device__ __align__(16) __nv_bfloat16 g_wa1t_hi[128 * 128], g_wa1t_lo[128 * 128];
__device__ __align__(16) __nv_bfloat16 g_wa2t_hi[128 * 128], g_wa2t_lo[128 * 128];

// ---------------------------------------------------------------------------
// helpers
// ---------------------------------------------------------------------------
__device__ __forceinline__ uint32_t smem_to_u32(const void* p) {
    uint32_t a;
    asm("{ .reg .u64 t; cvta.to.shared.u64 t, %1; cvt.u32.u64 %0, t; }"
        : "=r"(a) : "l"(p));
    return a;
}
__device__ __forceinline__ void ldsm_x4(uint32_t r[4], uint32_t addr) {
    asm volatile("ldmatrix.sync.aligned.m8n8.x4.shared.b16 {%0,%1,%2,%3}, [%4];"
                 : "=r"(r[0]), "=r"(r[1]), "=r"(r[2]), "=r"(r[3]) : "r"(addr));
}
__device__ __forceinline__ void mma_bf16(float c[4], const uint32_t a[4],
                                         uint32_t b0, uint32_t b1) {
    asm volatile(
        "mma.sync.aligned.m16n8k16.row.col.f32.bf16.bf16.f32 "
        "{%0,%1,%2,%3}, {%4,%5,%6,%7}, {%8,%9}, {%0,%1,%2,%3};"
        : "+f"(c[0]), "+f"(c[1]), "+f"(c[2]), "+f"(c[3])
        : "r"(a[0]), "r"(a[1]), "r"(a[2]), "r"(a[3]), "r"(b0), "r"(b1));
}
__device__ __forceinline__ void cp_async16(uint32_t smem, const void* g) {
    asm volatile("cp.async.ca.shared.global [%0], [%1], 16;"
                 :: "r"(smem), "l"(g));
}
#define CP_COMMIT() asm volatile("cp.async.commit_group;" ::: "memory")
#define CP_WAIT0()  asm volatile("cp.async.wait_group 0;" ::: "memory")
#define CP_WAIT3()  asm volatile("cp.async.wait_group 3;" ::: "memory")

__device__ __forceinline__ uint32_t pkbf(float a, float b) {
    __nv_bfloat162 t = __floats2bfloat162_rn(a, b);
    return *reinterpret_cast<uint32_t*>(&t);
}
__device__ __forceinline__ void red4(float* addr, float x, float y, float z,
                                     float w) {
    asm volatile("red.global.add.v4.f32 [%0], {%1, %2, %3, %4};"
                 :: "l"(addr), "f"(x), "f"(y), "f"(z), "f"(w) : "memory");
}

// Warp MMA over one 64-k chunk: warp tile (MT*16) rows x (NT*8) cols.
template <int MT, int SA, int NT>
__device__ __forceinline__ void mma_chunk(float (&acc)[MT][NT][4],
                                          uint32_t aw, uint32_t bw, int lane) {
    const int arow = lane & 15, ak = (lane >> 4) << 3;
    const int brow = (lane & 7) + ((lane >> 4) << 3);
    const int bk = ((lane >> 3) & 1) << 3;
#pragma unroll
    for (int kt = 0; kt < 4; kt++) {
        uint32_t a[MT][4], b[NT / 2][4];
#pragma unroll
        for (int mt = 0; mt < MT; mt++)
            ldsm_x4(a[mt], aw + ((mt * 16 + arow) * SA + kt * 16 + ak) * 2);
#pragma unroll
        for (int nb = 0; nb < NT / 2; nb++)
            ldsm_x4(b[nb], bw + ((nb * 16 + brow) * 72 + kt * 16 + bk) * 2);
#pragma unroll
        for (int mt = 0; mt < MT; mt++)
#pragma unroll
            for (int nb = 0; nb < NT / 2; nb++) {
                mma_bf16(acc[mt][2 * nb],     a[mt], b[nb][0], b[nb][1]);
                mma_bf16(acc[mt][2 * nb + 1], a[mt], b[nb][2], b[nb][3]);
            }
    }
}

#define SL_AHI 0
#define SL_ALO 18432
#define SL_BHI 36864
#define SL_BLO 55296
#define SL_END 73728

// Build A hi/lo smem slice (128 rows x 64 cols, stride 72) from fp32 src
__device__ __forceinline__ void build_A_fp32(unsigned char* sm,
                                             const float* __restrict__ src,
                                             int n0, int koff, int srcstride,
                                             int tid) {
#pragma unroll 2
    for (int i = 0; i < 8; i++) {
        int idx = tid + 256 * i;
        int row = idx >> 4, q = idx & 15;
        float4 v = *(const float4*)(src + (size_t)(n0 + row) * srcstride +
                                    koff + q * 4);
        __nv_bfloat16 h0 = __float2bfloat16(v.x), h1 = __float2bfloat16(v.y);
        __nv_bfloat16 h2 = __float2bfloat16(v.z), h3 = __float2bfloat16(v.w);
        uint2 hp, lp;
        hp.x = pkbf(v.x, v.y); hp.y = pkbf(v.z, v.w);
        lp.x = pkbf(v.x - __bfloat162float(h0), v.y - __bfloat162float(h1));
        lp.y = pkbf(v.z - __bfloat162float(h2), v.w - __bfloat162float(h3));
        int boff = (row * 72 + q * 4) * 2;
        *(uint2*)(sm + SL_AHI + boff) = hp;
        *(uint2*)(sm + SL_ALO + boff) = lp;
    }
}

// ---------------------------------------------------------------------------
// K0: merged setup #1 — weight splits (w1p/wa1t/wa2t), Wc+Wpe, deg zero,
//     node encoder.  Block-range dispatch.
// ---------------------------------------------------------------------------
__global__ void __launch_bounds__(256)
k_setup1(const float* __restrict__ W1, const float* __restrict__ Wa1,
         const float* __restrict__ Wa2, const float* __restrict__ W2,
         const float* __restrict__ Wu, const float* __restrict__ We,
         const float* __restrict__ nf, const float* __restrict__ Wn,
         const float* __restrict__ bn, int degz, int N) {
    const int b = blockIdx.x, tid = threadIdx.x;
    if (b < 384) {                            // weight transpose + hi/lo split
        int idx = b * 256 + tid;
        float v;
        __nv_bfloat16 *dh, *dl;
        int off;
        if (idx < 65536) {
            int n = idx >> 7, k = idx & 127;
            v = (n < 256) ? W1[k * 256 + n] : W1[(128 + k) * 256 + (n - 256)];
            dh = g_w1p_hi; dl = g_w1p_lo; off = idx;
        } else if (idx < 81920) {
            int i = idx - 65536;
            int n = i >> 7, k = i & 127;
            v = Wa1[k * 128 + n];
            dh = g_wa1t_hi; dl = g_wa1t_lo; off = i;
        } else {
            int i = idx - 81920;
            if (i >= 16384) return;
            int n = i >> 7, k = i & 127;
            v = Wa2[k * 128 + n];
            dh = g_wa2t_hi; dl = g_wa2t_lo; off = i;
        }
        __nv_bfloat16 hi = __float2bfloat16(v);
        dh[off] = hi;
        dl[off] = __float2bfloat16(v - __bfloat162float(hi));
    } else if (b < 528) {                     // Wc + Wpe
        int bid = b - 384;
        if (bid < 128) {
            int k = bid * 2 + (tid >> 7), c = tid & 127;
            __shared__ float w2row[2][256];
            w2row[tid >> 7][c] = W2[k * 256 + c];
            w2row[tid >> 7][c + 128] = W2[k * 256 + c + 128];
            __syncthreads();
            float s = 0.f;
            const float* wr = w2row[tid >> 7];
#pragma unroll 4
            for (int j = 0; j < 256; j++) s += wr[j] * Wu[(128 + j) * 128 + c];
            g_wc[k * 128 + c] = s;
        } else {
            int k = bid - 128, c = tid;
            __shared__ float wrow[64];
            if (tid < 64) wrow[tid] = We[k * 64 + tid];
            __syncthreads();
            float s = 0.f;
#pragma unroll 4
            for (int j = 0; j < 64; j++) s += wrow[j] * W1[(256 + j) * 256 + c];
            g_wpe[k * 256 + c] = s;
        }
    } else if (b < 528 + degz) {              // zero deg
        int i = (b - 528) * 256 + tid;
        if (i < N) g_deg[i] = 0;
    } else {                                  // node encoder
        __shared__ float Ws[32 * 128];
        __shared__ float nfs[16 * 32];
        __shared__ float bns[128];
        const int n0 = (b - 528 - degz) * 16;
#pragma unroll
        for (int i = 0; i < 16; i++) Ws[tid + 256 * i] = Wn[tid + 256 * i];
        if (tid < 128) bns[tid] = bn[tid];
#pragma unroll
        for (int i = 0; i < 2; i++) {
            int idx = tid + 256 * i;
            int node = idx >> 5, k = idx & 31;
            int n = n0 + node;
            nfs[idx] = (n < N) ? nf[(size_t)n * 32 + k] : 0.f;
        }
        __syncthreads();
#pragma unroll
        for (int i = 0; i < 8; i++) {
            int o = tid + 256 * i;
            int node = o >> 7, c = o & 127;
            int n = n0 + node;
            if (n >= N) continue;
            float s = bns[c];
            const float* nr = nfs + node * 32;
#pragma unroll
            for (int k = 0; k < 32; k++) s = fmaf(nr[k], Ws[k * 128 + c], s);
            size_t gi = (size_t)n * 128 + c;
            g_h[gi] = s;
            __nv_bfloat16 hi = __float2bfloat16(s);
            g_h_hi[gi] = hi;
            g_h_lo[gi] = __float2bfloat16(s - __bfloat162float(hi));
        }
    }
}

// ---------------------------------------------------------------------------
// K0b: merged setup #2 — pack wut2/bc/bpe + degree count.
// ---------------------------------------------------------------------------
__global__ void k_setup2(const float* __restrict__ Wu, const float* __restrict__ b2,
                         const float* __restrict__ W1, const float* __restrict__ b1,
                         const float* __restrict__ be,
                         const int* __restrict__ to_idx, int E) {
    const int b = blockIdx.x, tid = threadIdx.x;
    if (b < 194) {
        int idx = b * 256 + tid;
        if (idx < 49152) {
            int n = idx & 127, k = idx >> 7;
            float v = (k < 128) ? Wu[k * 128 + n] : g_wc[(k - 128) * 128 + n];
            __nv_bfloat16 hi = __float2bfloat16(v);
            int off = n * 384 + k;
            g_wut2_hi[off] = hi;
            g_wut2_lo[off] = __float2bfloat16(v - __bfloat162float(hi));
        } else if (idx < 49280) {
            int c = idx - 49152;
            float s = 0.f;
#pragma unroll 4
            for (int j = 0; j < 256; j++) s += b2[j] * Wu[(128 + j) * 128 + c];
            g_bc[c] = s;
        } else if (idx < 49536) {
            int c = idx - 49280;
            float s = b1[c];
#pragma unroll 4
            for (int j = 0; j < 64; j++) s += be[j] * W1[(256 + j) * 256 + c];
            g_bpe[c] = s;
        }
    } else {
        int i = (b - 194) * 256 + tid;
        if (i < E) atomicAdd(&g_deg[to_idx[i]], 1);
    }
}

// ---------------------------------------------------------------------------
// K4: P12 = h @ [W1_top|W1_mid] (+bpe on P2 half); cb<2 also zero aggH half.
// ---------------------------------------------------------------------------
__global__ void __launch_bounds__(256, 2)
k_nodeprod(int N) {
    extern __shared__ unsigned char sm[];
    const uint32_t base = smem_to_u32(sm);
    const int tid = threadIdx.x, lane = tid & 31, wid = tid >> 5;
    const int cb = blockIdx.x & 3, rb = blockIdx.x >> 2;
    const int n0 = rb * 128;
    const int wm = wid >> 2, wn = wid & 3;

    if (cb < 2) {
        const float4 z = make_float4(0.f, 0.f, 0.f, 0.f);
#pragma unroll
        for (int i = 0; i < 16; i++) {
            int idx = tid + 256 * i;
            int row = idx >> 5, q = idx & 31;
            int n = n0 + row;
            if (n < N)
                *(float4*)(g_aggH + (size_t)n * 256 + cb * 128 + q * 4) = z;
        }
    }

    float acc[4][4][4];
#pragma unroll
    for (int i = 0; i < 4; i++)
#pragma unroll
        for (int j = 0; j < 4; j++)
#pragma unroll
            for (int k = 0; k < 4; k++) acc[i][j][k] = 0.f;

    for (int kc = 0; kc < 2; kc++) {
        {
            int row = tid & 127, which = tid >> 7;
            const __nv_bfloat16* src =
                (which ? g_w1p_lo : g_w1p_hi) +
                (size_t)(cb * 128 + row) * 128 + kc * 64;
            uint32_t dst = base + (which ? SL_BLO : SL_BHI) + row * 144;
#pragma unroll
            for (int j = 0; j < 8; j++) cp_async16(dst + j * 16, src + j * 8);
            CP_COMMIT();
        }
        {
            int row = tid & 127, which = tid >> 7;
            const __nv_bfloat16* src =
                (which ? g_h_lo : g_h_hi) + (size_t)(n0 + row) * 128 + kc * 64;
            unsigned char* dst = sm + (which ? SL_ALO : SL_AHI) + row * 144;
#pragma unroll
            for (int j = 0; j < 8; j++)
                *(uint4*)(dst + j * 16) = *(const uint4*)(src + j * 8);
        }
        CP_WAIT0();
        __syncthreads();
#pragma unroll
        for (int p = 0; p < 3; p++) {
            uint32_t aw = base + (p == 1 ? SL_ALO : SL_AHI) + (wm * 64 * 72) * 2;
            uint32_t bw = base + (p == 2 ? SL_BLO : SL_BHI) + (wn * 32) * 144;
            mma_chunk<4, 72, 4>(acc, aw, bw, lane);
        }
        __syncthreads();
    }
#pragma unroll
    for (int mt = 0; mt < 4; mt++) {
        int r0 = wm * 64 + mt * 16 + (lane >> 2);
        int n1 = n0 + r0, n2 = n1 + 8;
#pragma unroll
        for (int nt = 0; nt < 4; nt++) {
            int colp = wn * 32 + nt * 8 + 2 * (lane & 3);
            int col = cb * 128 + colp;
            float2 badd = make_float2(0.f, 0.f);
            if (cb >= 2) badd = *(const float2*)(g_bpe + (cb - 2) * 128 + colp);
            if (n1 < N)
                *(float2*)(g_P + (size_t)n1 * 512 + col) =
                    make_float2(acc[mt][nt][0] + badd.x, acc[mt][nt][1] + badd.y);
            if (n2 < N)
                *(float2*)(g_P + (size_t)n2 * 512 + col) =
                    make_float2(acc[mt][nt][2] + badd.x, acc[mt][nt][3] + badd.y);
        }
    }
}

// ---------------------------------------------------------------------------
// K5: hidden = relu(P1[from]+P2[to]+ef@Wpe); aggH[to] += hidden (red.v4).
//     Wpe in registers; P1/P2 staged through a 5-slot cp.async smem ring
//     (prefetch distance 4 => 8 outstanding 16B loads/thread, 0 reg cost).
// ---------------------------------------------------------------------------
__global__ void __launch_bounds__(256)
k_hidden(const int* __restrict__ from_idx, const int* __restrict__ to_idx,
         const float* __restrict__ ef, int E) {
    __shared__ float ef_sm[64 * 16];
    __shared__ int from_sm[64], to_sm[64];
    __shared__ __align__(16) float stage[5][256 * 8];
    const int tid = threadIdx.x;
    const int e0 = blockIdx.x * 64;
    const int cg = tid & 63, sub = tid >> 6;

    if (tid < 64) {
        int ed = e0 + tid;
        from_sm[tid] = (ed < E) ? from_idx[ed] : -1;
        to_sm[tid]   = (ed < E) ? to_idx[ed] : 0;
    }
#pragma unroll
    for (int i = 0; i < 4; i++) {
        int idx = tid + 256 * i;
        int ed = e0 + (idx >> 4);
        ef_sm[idx] = (ed < E) ? ef[(size_t)ed * 16 + (idx & 15)] : 0.f;
    }
    float4 w[16];
#pragma unroll
    for (int k = 0; k < 16; k++)
        w[k] = *(const float4*)(g_wpe + k * 256 + cg * 4);
    __syncthreads();

    const uint32_t st_base = smem_to_u32(stage) + tid * 32;
    // prologue: stages for iterations 0..3
#pragma unroll
    for (int s = 0; s < 4; s++) {
        int le = s * 4 + sub;
        int f = from_sm[le], t = to_sm[le];
        int fc = (f < 0) ? 0 : f;
        cp_async16(st_base + s * 8192, g_P + (size_t)fc * 512 + cg * 4);
        cp_async16(st_base + s * 8192 + 16,
                   g_P + (size_t)t * 512 + 256 + cg * 4);
        CP_COMMIT();
    }
#pragma unroll
    for (int i = 0; i < 16; i++) {
        CP_WAIT3();                       // group for iteration i complete
        const int slot = i % 5;
        float4 p1 = *(const float4*)((const unsigned char*)stage +
                                     (st_base - smem_to_u32(stage)) +
                                     slot * 8192);
        float4 p2 = *(const float4*)((const unsigned char*)stage +
                                     (st_base - smem_to_u32(stage)) +
                                     slot * 8192 + 16);
        int le = i * 4 + sub;
        int f = from_sm[le], t = to_sm[le];
        // prefetch iteration i+4 into slot (i+4)%5 (consumed at i-1)
        if (i + 4 < 16) {
            int le4 = (i + 4) * 4 + sub;
            int f4 = from_sm[le4], t4 = to_sm[le4];
            int fc = (f4 < 0) ? 0 : f4;
            int s4 = (i + 4) % 5;
            cp_async16(st_base + s4 * 8192, g_P + (size_t)fc * 512 + cg * 4);
            cp_async16(st_base + s4 * 8192 + 16,
                       g_P + (size_t)t4 * 512 + 256 + cg * 4);
        }
        CP_COMMIT();
        float s0 = p1.x + p2.x, s1 = p1.y + p2.y;
        float s2 = p1.z + p2.z, s3 = p1.w + p2.w;
        const float* er = ef_sm + le * 16;
#pragma unroll
        for (int k = 0; k < 16; k++) {
            float e = er[k];
            s0 = fmaf(e, w[k].x, s0);
            s1 = fmaf(e, w[k].y, s1);
            s2 = fmaf(e, w[k].z, s2);
            s3 = fmaf(e, w[k].w, s3);
        }
        if (f < 0) continue;
        s0 = fmaxf(s0, 0.f); s1 = fmaxf(s1, 0.f);
        s2 = fmaxf(s2, 0.f); s3 = fmaxf(s3, 0.f);
        red4(g_aggH + (size_t)t * 256 + cg * 4, s0, s1, s2, s3);
    }
}

// ---------------------------------------------------------------------------
// K6: node update, 64-row tiles (MT=2) for wave balance.
// ---------------------------------------------------------------------------
#define UP_AHI 0
#define UP_ALO 9216
#define UP_BHI 18432
#define UP_BLO 36864
#define UP_END 55296
__global__ void __launch_bounds__(256, 2)
k_upd2(const float* __restrict__ bu, const int* __restrict__ pos, int last,
       int N) {
    extern __shared__ unsigned char sm[];
    const uint32_t base = smem_to_u32(sm);
    const int tid = threadIdx.x, lane = tid & 31, wid = tid >> 5;
    const int n0 = blockIdx.x * 64;
    const int wm = wid >> 2, wn = wid & 3;
    float acc[2][4][4];
#pragma unroll
    for (int i = 0; i < 2; i++)
#pragma unroll
        for (int j = 0; j < 4; j++)
#pragma unroll
            for (int k = 0; k < 4; k++) acc[i][j][k] = 0.f;

    for (int kc = 0; kc < 6; kc++) {
        {
            int row = tid & 127, which = tid >> 7;
            const __nv_bfloat16* src =
                (which ? g_wut2_lo : g_wut2_hi) + (size_t)row * 384 + kc * 64;
            uint32_t dst = base + (which ? UP_BLO : UP_BHI) + row * 144;
#pragma unroll
            for (int j = 0; j < 8; j++) cp_async16(dst + j * 16, src + j * 8);
            CP_COMMIT();
        }
#pragma unroll
        for (int i = 0; i < 4; i++) {
            int idx = tid + 256 * i;
            int row = idx >> 4, q = idx & 15;
            float4 v;
            if (kc < 2)
                v = *(const float4*)(g_h + (size_t)(n0 + row) * 128 +
                                     kc * 64 + q * 4);
            else
                v = *(const float4*)(g_aggH + (size_t)(n0 + row) * 256 +
                                     (kc - 2) * 64 + q * 4);
            __nv_bfloat16 h0 = __float2bfloat16(v.x), h1 = __float2bfloat16(v.y);
            __nv_bfloat16 h2 = __float2bfloat16(v.z), h3 = __float2bfloat16(v.w);
            uint2 hp, lp;
            hp.x = pkbf(v.x, v.y); hp.y = pkbf(v.z, v.w);
            lp.x = pkbf(v.x - __bfloat162float(h0), v.y - __bfloat162float(h1));
            lp.y = pkbf(v.z - __bfloat162float(h2), v.w - __bfloat162float(h3));
            int boff = (row * 72 + q * 4) * 2;
            *(uint2*)(sm + UP_AHI + boff) = hp;
            *(uint2*)(sm + UP_ALO + boff) = lp;
        }
        CP_WAIT0();
        __syncthreads();
#pragma unroll
        for (int p = 0; p < 3; p++) {
            uint32_t aw = base + (p == 1 ? UP_ALO : UP_AHI) + (wm * 32 * 72) * 2;
            uint32_t bw = base + (p == 2 ? UP_BLO : UP_BHI) + (wn * 32) * 144;
            mma_chunk<2, 72, 4>(acc, aw, bw, lane);
        }
        __syncthreads();
    }
#pragma unroll
    for (int mt = 0; mt < 2; mt++) {
        int rr[2];
        rr[0] = wm * 32 + mt * 16 + (lane >> 2);
        rr[1] = rr[0] + 8;
#pragma unroll
        for (int nt = 0; nt < 4; nt++) {
            int col = wn * 32 + nt * 8 + 2 * (lane & 3);
            float2 bb = *(const float2*)(bu + col);
            float2 bc2 = *(const float2*)(g_bc + col);
#pragma unroll
            for (int h = 0; h < 2; h++) {
                int n = n0 + rr[h];
                if (n < N) {
                    float degf = (float)g_deg[n];
                    int pn = 0;
                    if (last) {
                        int slot = pos[n];
                        pn = (slot < 16384)
                                 ? ((slot >> 6) * 128 + (slot & 63))
                                 : (((slot - 16384) >> 6) * 128 + 64 + (slot & 63));
                    }
#pragma unroll
                    for (int z = 0; z < 2; z++) {
                        float v = g_h[(size_t)n * 128 + col + z] +
                                  acc[mt][nt][2 * h + z] + (z ? bb.y : bb.x) +
                                  degf * (z ? bc2.y : bc2.x);
                        if (last) {
                            g_flat[(size_t)pn * 128 + col + z] = v;
                        } else {
                            g_h[(size_t)n * 128 + col + z] = v;
                            __nv_bfloat16 hi = __float2bfloat16(v);
                            g_h_hi[(size_t)n * 128 + col + z] = hi;
                            g_h_lo[(size_t)n * 128 + col + z] =
                                __float2bfloat16(v - __bfloat162float(hi));
                        }
                    }
                }
            }
        }
    }
}

// ---------------------------------------------------------------------------
// K8: fused attention features + pair scoring.
// ---------------------------------------------------------------------------
#define AP_HIDHI 0
#define AP_HIDLO 34816
#define AP_B2HI  73728
#define AP_B2LO  92160
#define AP_BUFA  0
#define AP_BUFB  33024
#define AP_L     66048
#define AP_PC    82688
#define AP_SMEM  110592
__global__ void __launch_bounds__(256, 2)
k_attpair(const float* __restrict__ ba1, const float* __restrict__ ba2,
          const int* __restrict__ qsz, const int* __restrict__ csz,
          float* __restrict__ out) {
    extern __shared__ unsigned char sm[];
    const uint32_t base = smem_to_u32(sm);
    const int tid = threadIdx.x, lane = tid & 31, wid = tid >> 5;
    const int b = blockIdx.x;
    const int r0 = b * 128;
    const int qs = qsz[b], cs = csz[b];
    const int wm = wid >> 2, wn = wid & 3;
    __shared__ float redq[8], redc[8];

    float acc[4][4][4];
#pragma unroll
    for (int i = 0; i < 4; i++)
#pragma unroll
        for (int j = 0; j < 4; j++)
#pragma unroll
            for (int k = 0; k < 4; k++) acc[i][j][k] = 0.f;

    for (int kc = 0; kc < 2; kc++) {
        {
            int row = tid & 127, which = tid >> 7;
            const __nv_bfloat16* src =
                (which ? g_wa1t_lo : g_wa1t_hi) + (size_t)row * 128 + kc * 64;
            uint32_t dst = base + (which ? AP_B2LO : AP_B2HI) + row * 144;
#pragma unroll
            for (int j = 0; j < 8; j++) cp_async16(dst + j * 16, src + j * 8);
            CP_COMMIT();
        }
        build_A_fp32(sm, g_flat, r0, kc * 64, 128, tid);
        CP_WAIT0();
        __syncthreads();
#pragma unroll
        for (int p = 0; p < 3; p++) {
            uint32_t aw = base + (p == 1 ? SL_ALO : SL_AHI) + (wm * 64 * 72) * 2;
            uint32_t bw = base + (p == 2 ? AP_B2LO : AP_B2HI) + (wn * 32) * 144;
            mma_chunk<4, 72, 4>(acc, aw, bw, lane);
        }
        __syncthreads();
    }
#pragma unroll
    for (int mt = 0; mt < 4; mt++) {
        int rr0 = wm * 64 + mt * 16 + (lane >> 2);
#pragma unroll
        for (int nt = 0; nt < 4; nt++) {
            int col = wn * 32 + nt * 8 + 2 * (lane & 3);
            float2 bb = *(const float2*)(ba1 + col);
#pragma unroll
            for (int h = 0; h < 2; h++) {
                int row = rr0 + h * 8;
                float v0 = fmaxf(acc[mt][nt][2 * h]     + bb.x, 0.f);
                float v1 = fmaxf(acc[mt][nt][2 * h + 1] + bb.y, 0.f);
                __nv_bfloat16 b0 = __float2bfloat16(v0), b1 = __float2bfloat16(v1);
                int boff = (row * 136 + col) * 2;
                *(uint32_t*)(sm + AP_HIDHI + boff) = pkbf(v0, v1);
                *(uint32_t*)(sm + AP_HIDLO + boff) =
                    pkbf(v0 - __bfloat162float(b0), v1 - __bfloat162float(b1));
            }
            acc[mt][nt][0] = acc[mt][nt][1] = acc[mt][nt][2] = acc[mt][nt][3] = 0.f;
        }
    }
    __syncthreads();
    for (int kc = 0; kc < 2; kc++) {
        {
            int row = tid & 127, which = tid >> 7;
            const __nv_bfloat16* src =
                (which ? g_wa2t_lo : g_wa2t_hi) + (size_t)row * 128 + kc * 64;
            uint32_t dst = base + (which ? AP_B2LO : AP_B2HI) + row * 144;
#pragma unroll
            for (int j = 0; j < 8; j++) cp_async16(dst + j * 16, src + j * 8);
            CP_COMMIT();
        }
        CP_WAIT0();
        __syncthreads();
#pragma unroll
        for (int p = 0; p < 3; p++) {
            uint32_t aw = base + (p == 1 ? AP_HIDLO : AP_HIDHI) +
                          (wm * 64 * 136 + kc * 64) * 2;
            uint32_t bw = base + (p == 2 ? AP_B2LO : AP_B2HI) + (wn * 32) * 144;
            mma_chunk<4, 136, 4>(acc, aw, bw, lane);
        }
        __syncthreads();
    }
    float* bufA = (float*)(sm + AP_BUFA);
    float* bufB = (float*)(sm + AP_BUFB);
    float* L    = (float*)(sm + AP_L);
    float* pc   = (float*)(sm + AP_PC);
#pragma unroll
    for (int mt = 0; mt < 4; mt++) {
        int rr0 = wm * 64 + mt * 16 + (lane >> 2);
#pragma unroll
        for (int nt = 0; nt < 4; nt++) {
            int col = wn * 32 + nt * 8 + 2 * (lane & 3);
            float2 bb = *(const float2*)(ba2 + col);
#pragma unroll
            for (int h = 0; h < 2; h++) {
                int row = rr0 + h * 8;
                bool isq = row < 64;
                int q = isq ? row : row - 64;
                bool ok = q < (isq ? qs : cs);
                float v0 = ok ? acc[mt][nt][2 * h]     + bb.x : 0.f;
                float v1 = ok ? acc[mt][nt][2 * h + 1] + bb.y : 0.f;
                float* dst = isq ? bufA : bufB;
                dst[q * 129 + col]     = v0;
                dst[q * 129 + col + 1] = v1;
            }
        }
    }
    __syncthreads();
    {
        int q = tid >> 2, cg = tid & 3;
        float la[16];
#pragma unroll
        for (int j = 0; j < 16; j++) la[j] = 0.f;
        for (int k = 0; k < 128; k++) {
            float a = bufA[q * 129 + k];
            const float* bp = bufB + (cg * 16) * 129 + k;
#pragma unroll
            for (int j = 0; j < 16; j++) la[j] += a * bp[j * 129];
        }
        bool qv = q < qs;
#pragma unroll
        for (int j = 0; j < 16; j++) {
            int c = cg * 16 + j;
            L[q * 65 + c] = (qv && c < cs) ? la[j] * 10.0f : -1e9f;
        }
    }
    __syncthreads();
    for (int idx = tid; idx < 64 * 128; idx += 256) {
        int r = idx >> 7, k = idx & 127;
        bufA[r * 129 + k] = g_flat[(size_t)(r0 + r) * 128 + k];
        bufB[r * 129 + k] = g_flat[(size_t)(r0 + 64 + r) * 128 + k];
    }
    if (tid < 64) {
        int c = tid;
        float m = -1e30f;
        for (int q = 0; q < 64; q++) m = fmaxf(m, L[q * 65 + c]);
        float s = 0.f;
        for (int q = 0; q < 64; q++) {
            float ex = __expf(L[q * 65 + c] - m);
            s += ex;
            pc[q * 65 + c] = ex;
        }
        float inv = (c < cs) ? (1.0f / s) : 0.f;
        for (int q = 0; q < 64; q++) pc[q * 65 + c] *= inv;
    }
    __syncthreads();
    if (tid < 64) {
        float m = -1e30f;
        for (int c = 0; c < 64; c++) m = fmaxf(m, L[tid * 65 + c]);
        float s = 0.f;
        for (int c = 0; c < 64; c++) {
            float ex = __expf(L[tid * 65 + c] - m);
            s += ex;
            L[tid * 65 + c] = ex;
        }
        float inv = (tid < qs) ? (1.0f / s) : 0.f;
        for (int c = 0; c < 64; c++) L[tid * 65 + c] *= inv;
    }
    __syncthreads();
    float lq = 0.f, lc = 0.f;
    {
        const int d = tid & 127, gg = tid >> 7;
        float av[32];
#pragma unroll
        for (int j = 0; j < 32; j++) av[j] = 0.f;
        for (int c = 0; c < 64; c++) {
            float bb = bufB[c * 129 + d];
            const float* pp = L + (gg * 32) * 65 + c;
#pragma unroll
            for (int j = 0; j < 32; j++) av[j] += pp[j * 65] * bb;
        }
#pragma unroll
        for (int j = 0; j < 32; j++) {
            int q = gg * 32 + j;
            lq += fmaxf(bufA[q * 129 + d] - av[j], 0.f);
        }
#pragma unroll
        for (int j = 0; j < 32; j++) av[j] = 0.f;
        for (int q = 0; q < 64; q++) {
            float aa = bufA[q * 129 + d];
            const float* pp = pc + q * 65 + gg * 32;
#pragma unroll
            for (int j = 0; j < 32; j++) av[j] += pp[j] * aa;
        }
#pragma unroll
        for (int j = 0; j < 32; j++) {
            int c = gg * 32 + j;
            lc += fmaxf(bufB[c * 129 + d] - av[j], 0.f);
        }
    }
    for (int o = 16; o; o >>= 1) {
        lq += __shfl_down_sync(0xffffffffu, lq, o);
        lc += __shfl_down_sync(0xffffffffu, lc, o);
    }
    if (lane == 0) { redq[wid] = lq; redc[wid] = lc; }
    __syncthreads();
    if (tid == 0) {
        float sq = 0.f, sc = 0.f;
        for (int i = 0; i < 8; i++) { sq += redq[i]; sc += redc[i]; }
        out[b] = fminf(-sq, -sc);
    }
}

// ---------------------------------------------------------------------------
extern "C" void kernel_launch(void* const* d_in, const int* in_sizes, int n_in,
                              void* d_out, int out_size) {
    const float* nf       = (const float*)d_in[0];
    const float* ef       = (const float*)d_in[1];
    const int*   from_idx = (const int*)d_in[2];
    const int*   to_idx   = (const int*)d_in[3];
    const int*   pos      = (const int*)d_in[4];
    const int*   qsz      = (const int*)d_in[5];
    const int*   csz      = (const int*)d_in[6];
    const float* W_node = (const float*)d_in[7];
    const float* b_node = (const float*)d_in[8];
    const float* W_edge = (const float*)d_in[9];
    const float* b_edge = (const float*)d_in[10];
    const float* W_msg1 = (const float*)d_in[11];
    const float* b_msg1 = (const float*)d_in[12];
    const float* W_msg2 = (const float*)d_in[13];
    const float* b_msg2 = (const float*)d_in[14];
    const float* W_upd  = (const float*)d_in[15];
    const float* b_upd  = (const float*)d_in[16];
    const float* Wa1    = (const float*)d_in[17];
    const float* ba1    = (const float*)d_in[18];
    const float* Wa2    = (const float*)d_in[19];
    const float* ba2    = (const float*)d_in[20];

    const int N = in_sizes[0] / 32;
    const int E = in_sizes[1] / 16;

    cudaFuncSetAttribute(k_nodeprod, cudaFuncAttributeMaxDynamicSharedMemorySize, SL_END);
    cudaFuncSetAttribute(k_upd2,     cudaFuncAttributeMaxDynamicSharedMemorySize, UP_END);
    cudaFuncSetAttribute(k_attpair,  cudaFuncAttributeMaxDynamicSharedMemorySize, AP_SMEM);

    const int egrid   = (E + 63) / 64;
    const int ngrid   = (N + 127) / 128;
    const int ngrid64 = (N + 63) / 64;
    const int degz    = (N + 255) / 256;
    const int encg    = (N + 15) / 16;

    k_setup1<<<528 + degz + encg, 256>>>(W_msg1, Wa1, Wa2, W_msg2, W_upd,
                                         W_edge, nf, W_node, b_node, degz, N);
    k_setup2<<<194 + (E + 255) / 256, 256>>>(W_upd, b_msg2, W_msg1, b_msg1,
                                             b_edge, to_idx, E);

    for (int s = 0; s < 3; s++) {
        k_nodeprod<<<ngrid * 4, 256, SL_END>>>(N);
        k_hidden<<<egrid, 256>>>(from_idx, to_idx, ef, E);
        k_upd2<<<ngrid64, 256, UP_END>>>(b_upd, pos, s == 2 ? 1 : 0, N);
    }

    k_attpair<<<256, 256, AP_SMEM>>>(ba1, ba2, qsz, csz, (float*)d_out);
}

// round 16
// speedup vs baseline: 1.0863x; 1.0863x over previous
#include <cuda_runtime.h>
#include <cuda_bf16.h>
#include <cstdint>

#define NMAX 32768
#define EMAX 262144

// Scratch
__device__ float g_h   [NMAX * 128];
__device__ float g_aggH[NMAX * 256];
__device__ float g_flat[2 * 256 * 64 * 128];   // layout: pair*128 + (q | 64+c)
__device__ float g_P   [NMAX * 512];
__device__ float g_wc  [256 * 128];
__device__ float g_bc  [128];
__device__ float g_wpe [16 * 256];
__device__ float g_bpe [256];
__device__ int   g_deg [NMAX];
__device__ __align__(16) __nv_bfloat16 g_h_hi[NMAX * 128];
__device__ __align__(16) __nv_bfloat16 g_h_lo[NMAX * 128];
__device__ __align__(16) __nv_bfloat16 g_w1p_hi[512 * 128], g_w1p_lo[512 * 128];
__device__ __align__(16) __nv_bfloat16 g_wut2_hi[128 * 384], g_wut2_lo[128 * 384];
__device__ __align__(16) __nv_bfloat16 g_wa1t_hi[128 * 128], g_wa1t_lo[128 * 128];
__device__ __align__(16) __nv_bfloat16 g_wa2t_hi[128 * 128], g_wa2t_lo[128 * 128];

// ---------------------------------------------------------------------------
// helpers
// ---------------------------------------------------------------------------
__device__ __forceinline__ uint32_t smem_to_u32(const void* p) {
    uint32_t a;
    asm("{ .reg .u64 t; cvta.to.shared.u64 t, %1; cvt.u32.u64 %0, t; }"
        : "=r"(a) : "l"(p));
    return a;
}
__device__ __forceinline__ void ldsm_x4(uint32_t r[4], uint32_t addr) {
    asm volatile("ldmatrix.sync.aligned.m8n8.x4.shared.b16 {%0,%1,%2,%3}, [%4];"
                 : "=r"(r[0]), "=r"(r[1]), "=r"(r[2]), "=r"(r[3]) : "r"(addr));
}
__device__ __forceinline__ void mma_bf16(float c[4], const uint32_t a[4],
                                         uint32_t b0, uint32_t b1) {
    asm volatile(
        "mma.sync.aligned.m16n8k16.row.col.f32.bf16.bf16.f32 "
        "{%0,%1,%2,%3}, {%4,%5,%6,%7}, {%8,%9}, {%0,%1,%2,%3};"
        : "+f"(c[0]), "+f"(c[1]), "+f"(c[2]), "+f"(c[3])
        : "r"(a[0]), "r"(a[1]), "r"(a[2]), "r"(a[3]), "r"(b0), "r"(b1));
}
__device__ __forceinline__ void cp_async16(uint32_t smem, const void* g) {
    asm volatile("cp.async.ca.shared.global [%0], [%1], 16;"
                 :: "r"(smem), "l"(g));
}
#define CP_COMMIT() asm volatile("cp.async.commit_group;" ::: "memory")
#define CP_WAIT0()  asm volatile("cp.async.wait_group 0;" ::: "memory")

__device__ __forceinline__ uint32_t pkbf(float a, float b) {
    __nv_bfloat162 t = __floats2bfloat162_rn(a, b);
    return *reinterpret_cast<uint32_t*>(&t);
}
__device__ __forceinline__ void red4(float* addr, float x, float y, float z,
                                     float w) {
    asm volatile("red.global.add.v4.f32 [%0], {%1, %2, %3, %4};"
                 :: "l"(addr), "f"(x), "f"(y), "f"(z), "f"(w) : "memory");
}

// Warp MMA over one 64-k chunk: warp tile (MT*16) rows x (NT*8) cols.
template <int MT, int SA, int NT>
__device__ __forceinline__ void mma_chunk(float (&acc)[MT][NT][4],
                                          uint32_t aw, uint32_t bw, int lane) {
    const int arow = lane & 15, ak = (lane >> 4) << 3;
    const int brow = (lane & 7) + ((lane >> 4) << 3);
    const int bk = ((lane >> 3) & 1) << 3;
#pragma unroll
    for (int kt = 0; kt < 4; kt++) {
        uint32_t a[MT][4], b[NT / 2][4];
#pragma unroll
        for (int mt = 0; mt < MT; mt++)
            ldsm_x4(a[mt], aw + ((mt * 16 + arow) * SA + kt * 16 + ak) * 2);
#pragma unroll
        for (int nb = 0; nb < NT / 2; nb++)
            ldsm_x4(b[nb], bw + ((nb * 16 + brow) * 72 + kt * 16 + bk) * 2);
#pragma unroll
        for (int mt = 0; mt < MT; mt++)
#pragma unroll
            for (int nb = 0; nb < NT / 2; nb++) {
                mma_bf16(acc[mt][2 * nb],     a[mt], b[nb][0], b[nb][1]);
                mma_bf16(acc[mt][2 * nb + 1], a[mt], b[nb][2], b[nb][3]);
            }
    }
}

#define SL_AHI 0
#define SL_ALO 18432
#define SL_BHI 36864
#define SL_BLO 55296
#define SL_END 73728

// Build A hi/lo smem slice (128 rows x 64 cols, stride 72) from fp32 src
__device__ __forceinline__ void build_A_fp32(unsigned char* sm,
                                             const float* __restrict__ src,
                                             int n0, int koff, int srcstride,
                                             int tid) {
#pragma unroll 2
    for (int i = 0; i < 8; i++) {
        int idx = tid + 256 * i;
        int row = idx >> 4, q = idx & 15;
        float4 v = *(const float4*)(src + (size_t)(n0 + row) * srcstride +
                                    koff + q * 4);
        __nv_bfloat16 h0 = __float2bfloat16(v.x), h1 = __float2bfloat16(v.y);
        __nv_bfloat16 h2 = __float2bfloat16(v.z), h3 = __float2bfloat16(v.w);
        uint2 hp, lp;
        hp.x = pkbf(v.x, v.y); hp.y = pkbf(v.z, v.w);
        lp.x = pkbf(v.x - __bfloat162float(h0), v.y - __bfloat162float(h1));
        lp.y = pkbf(v.z - __bfloat162float(h2), v.w - __bfloat162float(h3));
        int boff = (row * 72 + q * 4) * 2;
        *(uint2*)(sm + SL_AHI + boff) = hp;
        *(uint2*)(sm + SL_ALO + boff) = lp;
    }
}

// ---------------------------------------------------------------------------
// K0: merged setup #1 — weight splits (w1p/wa1t/wa2t), Wc+Wpe, deg zero,
//     node encoder.  Block-range dispatch.
// ---------------------------------------------------------------------------
__global__ void __launch_bounds__(256)
k_setup1(const float* __restrict__ W1, const float* __restrict__ Wa1,
         const float* __restrict__ Wa2, const float* __restrict__ W2,
         const float* __restrict__ Wu, const float* __restrict__ We,
         const float* __restrict__ nf, const float* __restrict__ Wn,
         const float* __restrict__ bn, int degz, int N) {
    const int b = blockIdx.x, tid = threadIdx.x;
    if (b < 384) {                            // weight transpose + hi/lo split
        int idx = b * 256 + tid;
        float v;
        __nv_bfloat16 *dh, *dl;
        int off;
        if (idx < 65536) {
            int n = idx >> 7, k = idx & 127;
            v = (n < 256) ? W1[k * 256 + n] : W1[(128 + k) * 256 + (n - 256)];
            dh = g_w1p_hi; dl = g_w1p_lo; off = idx;
        } else if (idx < 81920) {
            int i = idx - 65536;
            int n = i >> 7, k = i & 127;
            v = Wa1[k * 128 + n];
            dh = g_wa1t_hi; dl = g_wa1t_lo; off = i;
        } else {
            int i = idx - 81920;
            if (i >= 16384) return;
            int n = i >> 7, k = i & 127;
            v = Wa2[k * 128 + n];
            dh = g_wa2t_hi; dl = g_wa2t_lo; off = i;
        }
        __nv_bfloat16 hi = __float2bfloat16(v);
        dh[off] = hi;
        dl[off] = __float2bfloat16(v - __bfloat162float(hi));
    } else if (b < 528) {                     // Wc + Wpe
        int bid = b - 384;
        if (bid < 128) {
            int k = bid * 2 + (tid >> 7), c = tid & 127;
            __shared__ float w2row[2][256];
            w2row[tid >> 7][c] = W2[k * 256 + c];
            w2row[tid >> 7][c + 128] = W2[k * 256 + c + 128];
            __syncthreads();
            float s = 0.f;
            const float* wr = w2row[tid >> 7];
#pragma unroll 4
            for (int j = 0; j < 256; j++) s += wr[j] * Wu[(128 + j) * 128 + c];
            g_wc[k * 128 + c] = s;
        } else {
            int k = bid - 128, c = tid;
            __shared__ float wrow[64];
            if (tid < 64) wrow[tid] = We[k * 64 + tid];
            __syncthreads();
            float s = 0.f;
#pragma unroll 4
            for (int j = 0; j < 64; j++) s += wrow[j] * W1[(256 + j) * 256 + c];
            g_wpe[k * 256 + c] = s;
        }
    } else if (b < 528 + degz) {              // zero deg
        int i = (b - 528) * 256 + tid;
        if (i < N) g_deg[i] = 0;
    } else {                                  // node encoder
        __shared__ float Ws[32 * 128];
        __shared__ float nfs[16 * 32];
        __shared__ float bns[128];
        const int n0 = (b - 528 - degz) * 16;
#pragma unroll
        for (int i = 0; i < 16; i++) Ws[tid + 256 * i] = Wn[tid + 256 * i];
        if (tid < 128) bns[tid] = bn[tid];
#pragma unroll
        for (int i = 0; i < 2; i++) {
            int idx = tid + 256 * i;
            int node = idx >> 5, k = idx & 31;
            int n = n0 + node;
            nfs[idx] = (n < N) ? nf[(size_t)n * 32 + k] : 0.f;
        }
        __syncthreads();
#pragma unroll
        for (int i = 0; i < 8; i++) {
            int o = tid + 256 * i;
            int node = o >> 7, c = o & 127;
            int n = n0 + node;
            if (n >= N) continue;
            float s = bns[c];
            const float* nr = nfs + node * 32;
#pragma unroll
            for (int k = 0; k < 32; k++) s = fmaf(nr[k], Ws[k * 128 + c], s);
            size_t gi = (size_t)n * 128 + c;
            g_h[gi] = s;
            __nv_bfloat16 hi = __float2bfloat16(s);
            g_h_hi[gi] = hi;
            g_h_lo[gi] = __float2bfloat16(s - __bfloat162float(hi));
        }
    }
}

// ---------------------------------------------------------------------------
// K0b: merged setup #2 — pack wut2/bc/bpe + degree count.
// ---------------------------------------------------------------------------
__global__ void k_setup2(const float* __restrict__ Wu, const float* __restrict__ b2,
                         const float* __restrict__ W1, const float* __restrict__ b1,
                         const float* __restrict__ be,
                         const int* __restrict__ to_idx, int E) {
    const int b = blockIdx.x, tid = threadIdx.x;
    if (b < 194) {
        int idx = b * 256 + tid;
        if (idx < 49152) {
            int n = idx & 127, k = idx >> 7;
            float v = (k < 128) ? Wu[k * 128 + n] : g_wc[(k - 128) * 128 + n];
            __nv_bfloat16 hi = __float2bfloat16(v);
            int off = n * 384 + k;
            g_wut2_hi[off] = hi;
            g_wut2_lo[off] = __float2bfloat16(v - __bfloat162float(hi));
        } else if (idx < 49280) {
            int c = idx - 49152;
            float s = 0.f;
#pragma unroll 4
            for (int j = 0; j < 256; j++) s += b2[j] * Wu[(128 + j) * 128 + c];
            g_bc[c] = s;
        } else if (idx < 49536) {
            int c = idx - 49280;
            float s = b1[c];
#pragma unroll 4
            for (int j = 0; j < 64; j++) s += be[j] * W1[(256 + j) * 256 + c];
            g_bpe[c] = s;
        }
    } else {
        int i = (b - 194) * 256 + tid;
        if (i < E) atomicAdd(&g_deg[to_idx[i]], 1);
    }
}

// ---------------------------------------------------------------------------
// K4: P12 = h @ [W1_top|W1_mid] (+bpe on P2 half); cb<2 also zero aggH half.
// ---------------------------------------------------------------------------
__global__ void __launch_bounds__(256, 2)
k_nodeprod(int N) {
    extern __shared__ unsigned char sm[];
    const uint32_t base = smem_to_u32(sm);
    const int tid = threadIdx.x, lane = tid & 31, wid = tid >> 5;
    const int cb = blockIdx.x & 3, rb = blockIdx.x >> 2;
    const int n0 = rb * 128;
    const int wm = wid >> 2, wn = wid & 3;

    if (cb < 2) {
        const float4 z = make_float4(0.f, 0.f, 0.f, 0.f);
#pragma unroll
        for (int i = 0; i < 16; i++) {
            int idx = tid + 256 * i;
            int row = idx >> 5, q = idx & 31;
            int n = n0 + row;
            if (n < N)
                *(float4*)(g_aggH + (size_t)n * 256 + cb * 128 + q * 4) = z;
        }
    }

    float acc[4][4][4];
#pragma unroll
    for (int i = 0; i < 4; i++)
#pragma unroll
        for (int j = 0; j < 4; j++)
#pragma unroll
            for (int k = 0; k < 4; k++) acc[i][j][k] = 0.f;

    for (int kc = 0; kc < 2; kc++) {
        {
            int row = tid & 127, which = tid >> 7;
            const __nv_bfloat16* src =
                (which ? g_w1p_lo : g_w1p_hi) +
                (size_t)(cb * 128 + row) * 128 + kc * 64;
            uint32_t dst = base + (which ? SL_BLO : SL_BHI) + row * 144;
#pragma unroll
            for (int j = 0; j < 8; j++) cp_async16(dst + j * 16, src + j * 8);
            CP_COMMIT();
        }
        {
            int row = tid & 127, which = tid >> 7;
            const __nv_bfloat16* src =
                (which ? g_h_lo : g_h_hi) + (size_t)(n0 + row) * 128 + kc * 64;
            unsigned char* dst = sm + (which ? SL_ALO : SL_AHI) + row * 144;
#pragma unroll
            for (int j = 0; j < 8; j++)
                *(uint4*)(dst + j * 16) = *(const uint4*)(src + j * 8);
        }
        CP_WAIT0();
        __syncthreads();
#pragma unroll
        for (int p = 0; p < 3; p++) {
            uint32_t aw = base + (p == 1 ? SL_ALO : SL_AHI) + (wm * 64 * 72) * 2;
            uint32_t bw = base + (p == 2 ? SL_BLO : SL_BHI) + (wn * 32) * 144;
            mma_chunk<4, 72, 4>(acc, aw, bw, lane);
        }
        __syncthreads();
    }
#pragma unroll
    for (int mt = 0; mt < 4; mt++) {
        int r0 = wm * 64 + mt * 16 + (lane >> 2);
        int n1 = n0 + r0, n2 = n1 + 8;
#pragma unroll
        for (int nt = 0; nt < 4; nt++) {
            int colp = wn * 32 + nt * 8 + 2 * (lane & 3);
            int col = cb * 128 + colp;
            float2 badd = make_float2(0.f, 0.f);
            if (cb >= 2) badd = *(const float2*)(g_bpe + (cb - 2) * 128 + colp);
            if (n1 < N)
                *(float2*)(g_P + (size_t)n1 * 512 + col) =
                    make_float2(acc[mt][nt][0] + badd.x, acc[mt][nt][1] + badd.y);
            if (n2 < N)
                *(float2*)(g_P + (size_t)n2 * 512 + col) =
                    make_float2(acc[mt][nt][2] + badd.x, acc[mt][nt][3] + badd.y);
        }
    }
}

// ---------------------------------------------------------------------------
// K5: hidden = relu(P1[from]+P2[to]+ef@Wpe); aggH[to] += hidden (red.v4).
//     Wpe in registers + depth-2 software-pipelined P1/P2 prefetch.
//     ef rows read as float4 (4 LDS.128 instead of 16 LDS.32).
// ---------------------------------------------------------------------------
__global__ void __launch_bounds__(256)
k_hidden(const int* __restrict__ from_idx, const int* __restrict__ to_idx,
         const float* __restrict__ ef, int E) {
    __shared__ __align__(16) float ef_sm[64 * 16];
    __shared__ int from_sm[64], to_sm[64];
    const int tid = threadIdx.x;
    const int e0 = blockIdx.x * 64;
    const int cg = tid & 63, sub = tid >> 6;

    if (tid < 64) {
        int ed = e0 + tid;
        from_sm[tid] = (ed < E) ? from_idx[ed] : -1;
        to_sm[tid]   = (ed < E) ? to_idx[ed] : 0;
    }
#pragma unroll
    for (int i = 0; i < 4; i++) {
        int idx = tid + 256 * i;
        int ed = e0 + (idx >> 4);
        ef_sm[idx] = (ed < E) ? ef[(size_t)ed * 16 + (idx & 15)] : 0.f;
    }
    float4 w[16];
#pragma unroll
    for (int k = 0; k < 16; k++)
        w[k] = *(const float4*)(g_wpe + k * 256 + cg * 4);
    __syncthreads();

    // depth-2 software pipeline: iterations i and i+1 in flight
    int fb[2], tb[2];
    float4 p1b[2], p2b[2];
#pragma unroll
    for (int j = 0; j < 2; j++) {
        fb[j] = from_sm[j * 4 + sub];
        tb[j] = to_sm[j * 4 + sub];
        p1b[j] = make_float4(0.f, 0.f, 0.f, 0.f);
        p2b[j] = p1b[j];
        if (fb[j] >= 0) {
            p1b[j] = *(const float4*)(g_P + (size_t)fb[j] * 512 + cg * 4);
            p2b[j] = *(const float4*)(g_P + (size_t)tb[j] * 512 + 256 + cg * 4);
        }
    }
#pragma unroll
    for (int i = 0; i < 16; i++) {
        const int cur = i & 1;
        int f = fb[cur], t = tb[cur];
        float4 p1 = p1b[cur], p2 = p2b[cur];
        if (i + 2 < 16) {
            int fn = from_sm[(i + 2) * 4 + sub];
            int tn = to_sm[(i + 2) * 4 + sub];
            fb[cur] = fn;
            tb[cur] = tn;
            if (fn >= 0) {
                p1b[cur] = *(const float4*)(g_P + (size_t)fn * 512 + cg * 4);
                p2b[cur] = *(const float4*)(g_P + (size_t)tn * 512 + 256 + cg * 4);
            }
        }
        if (f < 0) continue;
        float s0 = p1.x + p2.x, s1 = p1.y + p2.y;
        float s2 = p1.z + p2.z, s3 = p1.w + p2.w;
        const float4* er4 = (const float4*)(ef_sm + (i * 4 + sub) * 16);
#pragma unroll
        for (int k4 = 0; k4 < 4; k4++) {
            float4 ev = er4[k4];
            const float4* wk = w + k4 * 4;
            s0 = fmaf(ev.x, wk[0].x, s0);
            s1 = fmaf(ev.x, wk[0].y, s1);
            s2 = fmaf(ev.x, wk[0].z, s2);
            s3 = fmaf(ev.x, wk[0].w, s3);
            s0 = fmaf(ev.y, wk[1].x, s0);
            s1 = fmaf(ev.y, wk[1].y, s1);
            s2 = fmaf(ev.y, wk[1].z, s2);
            s3 = fmaf(ev.y, wk[1].w, s3);
            s0 = fmaf(ev.z, wk[2].x, s0);
            s1 = fmaf(ev.z, wk[2].y, s1);
            s2 = fmaf(ev.z, wk[2].z, s2);
            s3 = fmaf(ev.z, wk[2].w, s3);
            s0 = fmaf(ev.w, wk[3].x, s0);
            s1 = fmaf(ev.w, wk[3].y, s1);
            s2 = fmaf(ev.w, wk[3].z, s2);
            s3 = fmaf(ev.w, wk[3].w, s3);
        }
        s0 = fmaxf(s0, 0.f); s1 = fmaxf(s1, 0.f);
        s2 = fmaxf(s2, 0.f); s3 = fmaxf(s3, 0.f);
        red4(g_aggH + (size_t)t * 256 + cg * 4, s0, s1, s2, s3);
    }
}

// ---------------------------------------------------------------------------
// K6: node update, 64-row tiles (MT=2) for wave balance.
// ---------------------------------------------------------------------------
#define UP_AHI 0
#define UP_ALO 9216
#define UP_BHI 18432
#define UP_BLO 36864
#define UP_END 55296
__global__ void __launch_bounds__(256, 2)
k_upd2(const float* __restrict__ bu, const int* __restrict__ pos, int last,
       int N) {
    extern __shared__ unsigned char sm[];
    const uint32_t base = smem_to_u32(sm);
    const int tid = threadIdx.x, lane = tid & 31, wid = tid >> 5;
    const int n0 = blockIdx.x * 64;
    const int wm = wid >> 2, wn = wid & 3;
    float acc[2][4][4];
#pragma unroll
    for (int i = 0; i < 2; i++)
#pragma unroll
        for (int j = 0; j < 4; j++)
#pragma unroll
            for (int k = 0; k < 4; k++) acc[i][j][k] = 0.f;

    for (int kc = 0; kc < 6; kc++) {
        {
            int row = tid & 127, which = tid >> 7;
            const __nv_bfloat16* src =
                (which ? g_wut2_lo : g_wut2_hi) + (size_t)row * 384 + kc * 64;
            uint32_t dst = base + (which ? UP_BLO : UP_BHI) + row * 144;
#pragma unroll
            for (int j = 0; j < 8; j++) cp_async16(dst + j * 16, src + j * 8);
            CP_COMMIT();
        }
#pragma unroll
        for (int i = 0; i < 4; i++) {
            int idx = tid + 256 * i;
            int row = idx >> 4, q = idx & 15;
            float4 v;
            if (kc < 2)
                v = *(const float4*)(g_h + (size_t)(n0 + row) * 128 +
                                     kc * 64 + q * 4);
            else
                v = *(const float4*)(g_aggH + (size_t)(n0 + row) * 256 +
                                     (kc - 2) * 64 + q * 4);
            __nv_bfloat16 h0 = __float2bfloat16(v.x), h1 = __float2bfloat16(v.y);
            __nv_bfloat16 h2 = __float2bfloat16(v.z), h3 = __float2bfloat16(v.w);
            uint2 hp, lp;
            hp.x = pkbf(v.x, v.y); hp.y = pkbf(v.z, v.w);
            lp.x = pkbf(v.x - __bfloat162float(h0), v.y - __bfloat162float(h1));
            lp.y = pkbf(v.z - __bfloat162float(h2), v.w - __bfloat162float(h3));
            int boff = (row * 72 + q * 4) * 2;
            *(uint2*)(sm + UP_AHI + boff) = hp;
            *(uint2*)(sm + UP_ALO + boff) = lp;
        }
        CP_WAIT0();
        __syncthreads();
#pragma unroll
        for (int p = 0; p < 3; p++) {
            uint32_t aw = base + (p == 1 ? UP_ALO : UP_AHI) + (wm * 32 * 72) * 2;
            uint32_t bw = base + (p == 2 ? UP_BLO : UP_BHI) + (wn * 32) * 144;
            mma_chunk<2, 72, 4>(acc, aw, bw, lane);
        }
        __syncthreads();
    }
#pragma unroll
    for (int mt = 0; mt < 2; mt++) {
        int rr[2];
        rr[0] = wm * 32 + mt * 16 + (lane >> 2);
        rr[1] = rr[0] + 8;
#pragma unroll
        for (int nt = 0; nt < 4; nt++) {
            int col = wn * 32 + nt * 8 + 2 * (lane & 3);
            float2 bb = *(const float2*)(bu + col);
            float2 bc2 = *(const float2*)(g_bc + col);
#pragma unroll
            for (int h = 0; h < 2; h++) {
                int n = n0 + rr[h];
                if (n < N) {
                    float degf = (float)g_deg[n];
                    int pn = 0;
                    if (last) {
                        int slot = pos[n];
                        pn = (slot < 16384)
                                 ? ((slot >> 6) * 128 + (slot & 63))
                                 : (((slot - 16384) >> 6) * 128 + 64 + (slot & 63));
                    }
#pragma unroll
                    for (int z = 0; z < 2; z++) {
                        float v = g_h[(size_t)n * 128 + col + z] +
                                  acc[mt][nt][2 * h + z] + (z ? bb.y : bb.x) +
                                  degf * (z ? bc2.y : bc2.x);
                        if (last) {
                            g_flat[(size_t)pn * 128 + col + z] = v;
                        } else {
                            g_h[(size_t)n * 128 + col + z] = v;
                            __nv_bfloat16 hi = __float2bfloat16(v);
                            g_h_hi[(size_t)n * 128 + col + z] = hi;
                            g_h_lo[(size_t)n * 128 + col + z] =
                                __float2bfloat16(v - __bfloat162float(hi));
                        }
                    }
                }
            }
        }
    }
}

// ---------------------------------------------------------------------------
// K8: fused attention features + pair scoring.
// ---------------------------------------------------------------------------
#define AP_HIDHI 0
#define AP_HIDLO 34816
#define AP_B2HI  73728
#define AP_B2LO  92160
#define AP_BUFA  0
#define AP_BUFB  33024
#define AP_L     66048
#define AP_PC    82688
#define AP_SMEM  110592
__global__ void __launch_bounds__(256, 2)
k_attpair(const float* __restrict__ ba1, const float* __restrict__ ba2,
          const int* __restrict__ qsz, const int* __restrict__ csz,
          float* __restrict__ out) {
    extern __shared__ unsigned char sm[];
    const uint32_t base = smem_to_u32(sm);
    const int tid = threadIdx.x, lane = tid & 31, wid = tid >> 5;
    const int b = blockIdx.x;
    const int r0 = b * 128;
    const int qs = qsz[b], cs = csz[b];
    const int wm = wid >> 2, wn = wid & 3;
    __shared__ float redq[8], redc[8];

    float acc[4][4][4];
#pragma unroll
    for (int i = 0; i < 4; i++)
#pragma unroll
        for (int j = 0; j < 4; j++)
#pragma unroll
            for (int k = 0; k < 4; k++) acc[i][j][k] = 0.f;

    for (int kc = 0; kc < 2; kc++) {
        {
            int row = tid & 127, which = tid >> 7;
            const __nv_bfloat16* src =
                (which ? g_wa1t_lo : g_wa1t_hi) + (size_t)row * 128 + kc * 64;
            uint32_t dst = base + (which ? AP_B2LO : AP_B2HI) + row * 144;
#pragma unroll
            for (int j = 0; j < 8; j++) cp_async16(dst + j * 16, src + j * 8);
            CP_COMMIT();
        }
        build_A_fp32(sm, g_flat, r0, kc * 64, 128, tid);
        CP_WAIT0();
        __syncthreads();
#pragma unroll
        for (int p = 0; p < 3; p++) {
            uint32_t aw = base + (p == 1 ? SL_ALO : SL_AHI) + (wm * 64 * 72) * 2;
            uint32_t bw = base + (p == 2 ? AP_B2LO : AP_B2HI) + (wn * 32) * 144;
            mma_chunk<4, 72, 4>(acc, aw, bw, lane);
        }
        __syncthreads();
    }
#pragma unroll
    for (int mt = 0; mt < 4; mt++) {
        int rr0 = wm * 64 + mt * 16 + (lane >> 2);
#pragma unroll
        for (int nt = 0; nt < 4; nt++) {
            int col = wn * 32 + nt * 8 + 2 * (lane & 3);
            float2 bb = *(const float2*)(ba1 + col);
#pragma unroll
            for (int h = 0; h < 2; h++) {
                int row = rr0 + h * 8;
                float v0 = fmaxf(acc[mt][nt][2 * h]     + bb.x, 0.f);
                float v1 = fmaxf(acc[mt][nt][2 * h + 1] + bb.y, 0.f);
                __nv_bfloat16 b0 = __float2bfloat16(v0), b1 = __float2bfloat16(v1);
                int boff = (row * 136 + col) * 2;
                *(uint32_t*)(sm + AP_HIDHI + boff) = pkbf(v0, v1);
                *(uint32_t*)(sm + AP_HIDLO + boff) =
                    pkbf(v0 - __bfloat162float(b0), v1 - __bfloat162float(b1));
            }
            acc[mt][nt][0] = acc[mt][nt][1] = acc[mt][nt][2] = acc[mt][nt][3] = 0.f;
        }
    }
    __syncthreads();
    for (int kc = 0; kc < 2; kc++) {
        {
            int row = tid & 127, which = tid >> 7;
            const __nv_bfloat16* src =
                (which ? g_wa2t_lo : g_wa2t_hi) + (size_t)row * 128 + kc * 64;
            uint32_t dst = base + (which ? AP_B2LO : AP_B2HI) + row * 144;
#pragma unroll
            for (int j = 0; j < 8; j++) cp_async16(dst + j * 16, src + j * 8);
            CP_COMMIT();
        }
        CP_WAIT0();
        __syncthreads();
#pragma unroll
        for (int p = 0; p < 3; p++) {
            uint32_t aw = base + (p == 1 ? AP_HIDLO : AP_HIDHI) +
                          (wm * 64 * 136 + kc * 64) * 2;
            uint32_t bw = base + (p == 2 ? AP_B2LO : AP_B2HI) + (wn * 32) * 144;
            mma_chunk<4, 136, 4>(acc, aw, bw, lane);
        }
        __syncthreads();
    }
    float* bufA = (float*)(sm + AP_BUFA);
    float* bufB = (float*)(sm + AP_BUFB);
    float* L    = (float*)(sm + AP_L);
    float* pc   = (float*)(sm + AP_PC);
#pragma unroll
    for (int mt = 0; mt < 4; mt++) {
        int rr0 = wm * 64 + mt * 16 + (lane >> 2);
#pragma unroll
        for (int nt = 0; nt < 4; nt++) {
            int col = wn * 32 + nt * 8 + 2 * (lane & 3);
            float2 bb = *(const float2*)(ba2 + col);
#pragma unroll
            for (int h = 0; h < 2; h++) {
                int row = rr0 + h * 8;
                bool isq = row < 64;
                int q = isq ? row : row - 64;
                bool ok = q < (isq ? qs : cs);
                float v0 = ok ? acc[mt][nt][2 * h]     + bb.x : 0.f;
                float v1 = ok ? acc[mt][nt][2 * h + 1] + bb.y : 0.f;
                float* dst = isq ? bufA : bufB;
                dst[q * 129 + col]     = v0;
                dst[q * 129 + col + 1] = v1;
            }
        }
    }
    __syncthreads();
    {
        int q = tid >> 2, cg = tid & 3;
        float la[16];
#pragma unroll
        for (int j = 0; j < 16; j++) la[j] = 0.f;
        for (int k = 0; k < 128; k++) {
            float a = bufA[q * 129 + k];
            const float* bp = bufB + (cg * 16) * 129 + k;
#pragma unroll
            for (int j = 0; j < 16; j++) la[j] += a * bp[j * 129];
        }
        bool qv = q < qs;
#pragma unroll
        for (int j = 0; j < 16; j++) {
            int c = cg * 16 + j;
            L[q * 65 + c] = (qv && c < cs) ? la[j] * 10.0f : -1e9f;
        }
    }
    __syncthreads();
    for (int idx = tid; idx < 64 * 128; idx += 256) {
        int r = idx >> 7, k = idx & 127;
        bufA[r * 129 + k] = g_flat[(size_t)(r0 + r) * 128 + k];
        bufB[r * 129 + k] = g_flat[(size_t)(r0 + 64 + r) * 128 + k];
    }
    if (tid < 64) {
        int c = tid;
        float m = -1e30f;
        for (int q = 0; q < 64; q++) m = fmaxf(m, L[q * 65 + c]);
        float s = 0.f;
        for (int q = 0; q < 64; q++) {
            float ex = __expf(L[q * 65 + c] - m);
            s += ex;
            pc[q * 65 + c] = ex;
        }
        float inv = (c < cs) ? (1.0f / s) : 0.f;
        for (int q = 0; q < 64; q++) pc[q * 65 + c] *= inv;
    }
    __syncthreads();
    if (tid < 64) {
        float m = -1e30f;
        for (int c = 0; c < 64; c++) m = fmaxf(m, L[tid * 65 + c]);
        float s = 0.f;
        for (int c = 0; c < 64; c++) {
            float ex = __expf(L[tid * 65 + c] - m);
            s += ex;
            L[tid * 65 + c] = ex;
        }
        float inv = (tid < qs) ? (1.0f / s) : 0.f;
        for (int c = 0; c < 64; c++) L[tid * 65 + c] *= inv;
    }
    __syncthreads();
    float lq = 0.f, lc = 0.f;
    {
        const int d = tid & 127, gg = tid >> 7;
        float av[32];
#pragma unroll
        for (int j = 0; j < 32; j++) av[j] = 0.f;
        for (int c = 0; c < 64; c++) {
            float bb = bufB[c * 129 + d];
            const float* pp = L + (gg * 32) * 65 + c;
#pragma unroll
            for (int j = 0; j < 32; j++) av[j] += pp[j * 65] * bb;
        }
#pragma unroll
        for (int j = 0; j < 32; j++) {
            int q = gg * 32 + j;
            lq += fmaxf(bufA[q * 129 + d] - av[j], 0.f);
        }
#pragma unroll
        for (int j = 0; j < 32; j++) av[j] = 0.f;
        for (int q = 0; q < 64; q++) {
            float aa = bufA[q * 129 + d];
            const float* pp = pc + q * 65 + gg * 32;
#pragma unroll
            for (int j = 0; j < 32; j++) av[j] += pp[j] * aa;
        }
#pragma unroll
        for (int j = 0; j < 32; j++) {
            int c = gg * 32 + j;
            lc += fmaxf(bufB[c * 129 + d] - av[j], 0.f);
        }
    }
    for (int o = 16; o; o >>= 1) {
        lq += __shfl_down_sync(0xffffffffu, lq, o);
        lc += __shfl_down_sync(0xffffffffu, lc, o);
    }
    if (lane == 0) { redq[wid] = lq; redc[wid] = lc; }
    __syncthreads();
    if (tid == 0) {
        float sq = 0.f, sc = 0.f;
        for (int i = 0; i < 8; i++) { sq += redq[i]; sc += redc[i]; }
        out[b] = fminf(-sq, -sc);
    }
}

// ---------------------------------------------------------------------------
extern "C" void kernel_launch(void* const* d_in, const int* in_sizes, int n_in,
                              void* d_out, int out_size) {
    const float* nf       = (const float*)d_in[0];
    const float* ef       = (const float*)d_in[1];
    const int*   from_idx = (const int*)d_in[2];
    const int*   to_idx   = (const int*)d_in[3];
    const int*   pos      = (const int*)d_in[4];
    const int*   qsz      = (const int*)d_in[5];
    const int*   csz      = (const int*)d_in[6];
    const float* W_node = (const float*)d_in[7];
    const float* b_node = (const float*)d_in[8];
    const float* W_edge = (const float*)d_in[9];
    const float* b_edge = (const float*)d_in[10];
    const float* W_msg1 = (const float*)d_in[11];
    const float* b_msg1 = (const float*)d_in[12];
    const float* W_msg2 = (const float*)d_in[13];
    const float* b_msg2 = (const float*)d_in[14];
    const float* W_upd  = (const float*)d_in[15];
    const float* b_upd  = (const float*)d_in[16];
    const float* Wa1    = (const float*)d_in[17];
    const float* ba1    = (const float*)d_in[18];
    const float* Wa2    = (const float*)d_in[19];
    const float* ba2    = (const float*)d_in[20];

    const int N = in_sizes[0] / 32;
    const int E = in_sizes[1] / 16;

    cudaFuncSetAttribute(k_nodeprod, cudaFuncAttributeMaxDynamicSharedMemorySize, SL_END);
    cudaFuncSetAttribute(k_upd2,     cudaFuncAttributeMaxDynamicSharedMemorySize, UP_END);
    cudaFuncSetAttribute(k_attpair,  cudaFuncAttributeMaxDynamicSharedMemorySize, AP_SMEM);

    const int egrid   = (E + 63) / 64;
    const int ngrid   = (N + 127) / 128;
    const int ngrid64 = (N + 63) / 64;
    const int degz    = (N + 255) / 256;
    const int encg    = (N + 15) / 16;

    k_setup1<<<528 + degz + encg, 256>>>(W_msg1, Wa1, Wa2, W_msg2, W_upd,
                                         W_edge, nf, W_node, b_node, degz, N);
    k_setup2<<<194 + (E + 255) / 256, 256>>>(W_upd, b_msg2, W_msg1, b_msg1,
                                             b_edge, to_idx, E);

    for (int s = 0; s < 3; s++) {
        k_nodeprod<<<ngrid * 4, 256, SL_END>>>(N);
        k_hidden<<<egrid, 256>>>(from_idx, to_idx, ef, E);
        k_upd2<<<ngrid64, 256, UP_END>>>(b_upd, pos, s == 2 ? 1 : 0, N);
    }

    k_attpair<<<256, 256, AP_SMEM>>>(ba1, ba2, qsz, csz, (float*)d_out);
}

// round 17
// speedup vs baseline: 1.1205x; 1.0315x over previous
#include <cuda_runtime.h>
#include <cuda_bf16.h>
#include <cstdint>

#define NMAX 32768
#define EMAX 262144

// Scratch
__device__ float g_h   [NMAX * 128];
__device__ float g_aggH[NMAX * 256];
__device__ float g_flat[2 * 256 * 64 * 128];   // layout: pair*128 + (q | 64+c)
__device__ float g_P   [NMAX * 512];
__device__ float g_wc  [256 * 128];
__device__ float g_bc  [128];
__device__ float g_wpe [16 * 256];
__device__ float g_bpe [256];
__device__ int   g_deg [NMAX];
__device__ __align__(16) __nv_bfloat16 g_w1p_hi[512 * 128], g_w1p_lo[512 * 128];
__device__ __align__(16) __nv_bfloat16 g_wut2_hi[128 * 384], g_wut2_lo[128 * 384];
__device__ __align__(16) __nv_bfloat16 g_wa1t_hi[128 * 128], g_wa1t_lo[128 * 128];
__device__ __align__(16) __nv_bfloat16 g_wa2t_hi[128 * 128], g_wa2t_lo[128 * 128];

// ---------------------------------------------------------------------------
// helpers
// ---------------------------------------------------------------------------
__device__ __forceinline__ uint32_t smem_to_u32(const void* p) {
    uint32_t a;
    asm("{ .reg .u64 t; cvta.to.shared.u64 t, %1; cvt.u32.u64 %0, t; }"
        : "=r"(a) : "l"(p));
    return a;
}
__device__ __forceinline__ void ldsm_x4(uint32_t r[4], uint32_t addr) {
    asm volatile("ldmatrix.sync.aligned.m8n8.x4.shared.b16 {%0,%1,%2,%3}, [%4];"
                 : "=r"(r[0]), "=r"(r[1]), "=r"(r[2]), "=r"(r[3]) : "r"(addr));
}
__device__ __forceinline__ void mma_bf16(float c[4], const uint32_t a[4],
                                         uint32_t b0, uint32_t b1) {
    asm volatile(
        "mma.sync.aligned.m16n8k16.row.col.f32.bf16.bf16.f32 "
        "{%0,%1,%2,%3}, {%4,%5,%6,%7}, {%8,%9}, {%0,%1,%2,%3};"
        : "+f"(c[0]), "+f"(c[1]), "+f"(c[2]), "+f"(c[3])
        : "r"(a[0]), "r"(a[1]), "r"(a[2]), "r"(a[3]), "r"(b0), "r"(b1));
}
__device__ __forceinline__ void cp_async16(uint32_t smem, const void* g) {
    asm volatile("cp.async.ca.shared.global [%0], [%1], 16;"
                 :: "r"(smem), "l"(g));
}
#define CP_COMMIT() asm volatile("cp.async.commit_group;" ::: "memory")
#define CP_WAIT0()  asm volatile("cp.async.wait_group 0;" ::: "memory")

__device__ __forceinline__ uint32_t pkbf(float a, float b) {
    __nv_bfloat162 t = __floats2bfloat162_rn(a, b);
    return *reinterpret_cast<uint32_t*>(&t);
}
__device__ __forceinline__ void red4(float* addr, float x, float y, float z,
                                     float w) {
    asm volatile("red.global.add.v4.f32 [%0], {%1, %2, %3, %4};"
                 :: "l"(addr), "f"(x), "f"(y), "f"(z), "f"(w) : "memory");
}

// Warp MMA over one 64-k chunk: warp tile (MT*16) rows x (NT*8) cols.
template <int MT, int SA, int NT>
__device__ __forceinline__ void mma_chunk(float (&acc)[MT][NT][4],
                                          uint32_t aw, uint32_t bw, int lane) {
    const int arow = lane & 15, ak = (lane >> 4) << 3;
    const int brow = (lane & 7) + ((lane >> 4) << 3);
    const int bk = ((lane >> 3) & 1) << 3;
#pragma unroll
    for (int kt = 0; kt < 4; kt++) {
        uint32_t a[MT][4], b[NT / 2][4];
#pragma unroll
        for (int mt = 0; mt < MT; mt++)
            ldsm_x4(a[mt], aw + ((mt * 16 + arow) * SA + kt * 16 + ak) * 2);
#pragma unroll
        for (int nb = 0; nb < NT / 2; nb++)
            ldsm_x4(b[nb], bw + ((nb * 16 + brow) * 72 + kt * 16 + bk) * 2);
#pragma unroll
        for (int mt = 0; mt < MT; mt++)
#pragma unroll
            for (int nb = 0; nb < NT / 2; nb++) {
                mma_bf16(acc[mt][2 * nb],     a[mt], b[nb][0], b[nb][1]);
                mma_bf16(acc[mt][2 * nb + 1], a[mt], b[nb][2], b[nb][3]);
            }
    }
}

#define SL_AHI 0
#define SL_ALO 18432
#define SL_BHI 36864
#define SL_BLO 55296
#define SL_END 73728

// Build A hi/lo smem slice (128 rows x 64 cols, stride 72) from fp32 src
__device__ __forceinline__ void build_A_fp32(unsigned char* sm,
                                             const float* __restrict__ src,
                                             int n0, int koff, int srcstride,
                                             int tid) {
#pragma unroll 2
    for (int i = 0; i < 8; i++) {
        int idx = tid + 256 * i;
        int row = idx >> 4, q = idx & 15;
        float4 v = *(const float4*)(src + (size_t)(n0 + row) * srcstride +
                                    koff + q * 4);
        __nv_bfloat16 h0 = __float2bfloat16(v.x), h1 = __float2bfloat16(v.y);
        __nv_bfloat16 h2 = __float2bfloat16(v.z), h3 = __float2bfloat16(v.w);
        uint2 hp, lp;
        hp.x = pkbf(v.x, v.y); hp.y = pkbf(v.z, v.w);
        lp.x = pkbf(v.x - __bfloat162float(h0), v.y - __bfloat162float(h1));
        lp.y = pkbf(v.z - __bfloat162float(h2), v.w - __bfloat162float(h3));
        int boff = (row * 72 + q * 4) * 2;
        *(uint2*)(sm + SL_AHI + boff) = hp;
        *(uint2*)(sm + SL_ALO + boff) = lp;
    }
}

// ---------------------------------------------------------------------------
// K0: merged setup #1 — weight splits (w1p/wa1t/wa2t), Wc+Wpe, deg zero,
//     node encoder (fp32 only).  Block-range dispatch.
// ---------------------------------------------------------------------------
__global__ void __launch_bounds__(256)
k_setup1(const float* __restrict__ W1, const float* __restrict__ Wa1,
         const float* __restrict__ Wa2, const float* __restrict__ W2,
         const float* __restrict__ Wu, const float* __restrict__ We,
         const float* __restrict__ nf, const float* __restrict__ Wn,
         const float* __restrict__ bn, int degz, int N) {
    const int b = blockIdx.x, tid = threadIdx.x;
    if (b < 384) {                            // weight transpose + hi/lo split
        int idx = b * 256 + tid;
        float v;
        __nv_bfloat16 *dh, *dl;
        int off;
        if (idx < 65536) {
            int n = idx >> 7, k = idx & 127;
            v = (n < 256) ? W1[k * 256 + n] : W1[(128 + k) * 256 + (n - 256)];
            dh = g_w1p_hi; dl = g_w1p_lo; off = idx;
        } else if (idx < 81920) {
            int i = idx - 65536;
            int n = i >> 7, k = i & 127;
            v = Wa1[k * 128 + n];
            dh = g_wa1t_hi; dl = g_wa1t_lo; off = i;
        } else {
            int i = idx - 81920;
            if (i >= 16384) return;
            int n = i >> 7, k = i & 127;
            v = Wa2[k * 128 + n];
            dh = g_wa2t_hi; dl = g_wa2t_lo; off = i;
        }
        __nv_bfloat16 hi = __float2bfloat16(v);
        dh[off] = hi;
        dl[off] = __float2bfloat16(v - __bfloat162float(hi));
    } else if (b < 528) {                     // Wc + Wpe
        int bid = b - 384;
        if (bid < 128) {
            int k = bid * 2 + (tid >> 7), c = tid & 127;
            __shared__ float w2row[2][256];
            w2row[tid >> 7][c] = W2[k * 256 + c];
            w2row[tid >> 7][c + 128] = W2[k * 256 + c + 128];
            __syncthreads();
            float s = 0.f;
            const float* wr = w2row[tid >> 7];
#pragma unroll 4
            for (int j = 0; j < 256; j++) s += wr[j] * Wu[(128 + j) * 128 + c];
            g_wc[k * 128 + c] = s;
        } else {
            int k = bid - 128, c = tid;
            __shared__ float wrow[64];
            if (tid < 64) wrow[tid] = We[k * 64 + tid];
            __syncthreads();
            float s = 0.f;
#pragma unroll 4
            for (int j = 0; j < 64; j++) s += wrow[j] * W1[(256 + j) * 256 + c];
            g_wpe[k * 256 + c] = s;
        }
    } else if (b < 528 + degz) {              // zero deg
        int i = (b - 528) * 256 + tid;
        if (i < N) g_deg[i] = 0;
    } else {                                  // node encoder
        __shared__ float Ws[32 * 128];
        __shared__ float nfs[16 * 32];
        __shared__ float bns[128];
        const int n0 = (b - 528 - degz) * 16;
#pragma unroll
        for (int i = 0; i < 16; i++) Ws[tid + 256 * i] = Wn[tid + 256 * i];
        if (tid < 128) bns[tid] = bn[tid];
#pragma unroll
        for (int i = 0; i < 2; i++) {
            int idx = tid + 256 * i;
            int node = idx >> 5, k = idx & 31;
            int n = n0 + node;
            nfs[idx] = (n < N) ? nf[(size_t)n * 32 + k] : 0.f;
        }
        __syncthreads();
#pragma unroll
        for (int i = 0; i < 8; i++) {
            int o = tid + 256 * i;
            int node = o >> 7, c = o & 127;
            int n = n0 + node;
            if (n >= N) continue;
            float s = bns[c];
            const float* nr = nfs + node * 32;
#pragma unroll
            for (int k = 0; k < 32; k++) s = fmaf(nr[k], Ws[k * 128 + c], s);
            g_h[(size_t)n * 128 + c] = s;
        }
    }
}

// ---------------------------------------------------------------------------
// K0b: merged setup #2 — pack wut2/bc/bpe + degree count.
// ---------------------------------------------------------------------------
__global__ void k_setup2(const float* __restrict__ Wu, const float* __restrict__ b2,
                         const float* __restrict__ W1, const float* __restrict__ b1,
                         const float* __restrict__ be,
                         const int* __restrict__ to_idx, int E) {
    const int b = blockIdx.x, tid = threadIdx.x;
    if (b < 194) {
        int idx = b * 256 + tid;
        if (idx < 49152) {
            int n = idx & 127, k = idx >> 7;
            float v = (k < 128) ? Wu[k * 128 + n] : g_wc[(k - 128) * 128 + n];
            __nv_bfloat16 hi = __float2bfloat16(v);
            int off = n * 384 + k;
            g_wut2_hi[off] = hi;
            g_wut2_lo[off] = __float2bfloat16(v - __bfloat162float(hi));
        } else if (idx < 49280) {
            int c = idx - 49152;
            float s = 0.f;
#pragma unroll 4
            for (int j = 0; j < 256; j++) s += b2[j] * Wu[(128 + j) * 128 + c];
            g_bc[c] = s;
        } else if (idx < 49536) {
            int c = idx - 49280;
            float s = b1[c];
#pragma unroll 4
            for (int j = 0; j < 64; j++) s += be[j] * W1[(256 + j) * 256 + c];
            g_bpe[c] = s;
        }
    } else {
        int i = (b - 194) * 256 + tid;
        if (i < E) atomicAdd(&g_deg[to_idx[i]], 1);
    }
}

// ---------------------------------------------------------------------------
// K4: P12 = h @ [W1_top|W1_mid] (+bpe on P2 half); cb<2 also zero aggH half.
//     A tile built from fp32 g_h on the fly (bit-identical hi/lo split).
// ---------------------------------------------------------------------------
__global__ void __launch_bounds__(256, 2)
k_nodeprod(int N) {
    extern __shared__ unsigned char sm[];
    const uint32_t base = smem_to_u32(sm);
    const int tid = threadIdx.x, lane = tid & 31, wid = tid >> 5;
    const int cb = blockIdx.x & 3, rb = blockIdx.x >> 2;
    const int n0 = rb * 128;
    const int wm = wid >> 2, wn = wid & 3;

    if (cb < 2) {
        const float4 z = make_float4(0.f, 0.f, 0.f, 0.f);
#pragma unroll
        for (int i = 0; i < 16; i++) {
            int idx = tid + 256 * i;
            int row = idx >> 5, q = idx & 31;
            int n = n0 + row;
            if (n < N)
                *(float4*)(g_aggH + (size_t)n * 256 + cb * 128 + q * 4) = z;
        }
    }

    float acc[4][4][4];
#pragma unroll
    for (int i = 0; i < 4; i++)
#pragma unroll
        for (int j = 0; j < 4; j++)
#pragma unroll
            for (int k = 0; k < 4; k++) acc[i][j][k] = 0.f;

    for (int kc = 0; kc < 2; kc++) {
        {
            int row = tid & 127, which = tid >> 7;
            const __nv_bfloat16* src =
                (which ? g_w1p_lo : g_w1p_hi) +
                (size_t)(cb * 128 + row) * 128 + kc * 64;
            uint32_t dst = base + (which ? SL_BLO : SL_BHI) + row * 144;
#pragma unroll
            for (int j = 0; j < 8; j++) cp_async16(dst + j * 16, src + j * 8);
            CP_COMMIT();
        }
        build_A_fp32(sm, g_h, n0, kc * 64, 128, tid);
        CP_WAIT0();
        __syncthreads();
#pragma unroll
        for (int p = 0; p < 3; p++) {
            uint32_t aw = base + (p == 1 ? SL_ALO : SL_AHI) + (wm * 64 * 72) * 2;
            uint32_t bw = base + (p == 2 ? SL_BLO : SL_BHI) + (wn * 32) * 144;
            mma_chunk<4, 72, 4>(acc, aw, bw, lane);
        }
        __syncthreads();
    }
#pragma unroll
    for (int mt = 0; mt < 4; mt++) {
        int r0 = wm * 64 + mt * 16 + (lane >> 2);
        int n1 = n0 + r0, n2 = n1 + 8;
#pragma unroll
        for (int nt = 0; nt < 4; nt++) {
            int colp = wn * 32 + nt * 8 + 2 * (lane & 3);
            int col = cb * 128 + colp;
            float2 badd = make_float2(0.f, 0.f);
            if (cb >= 2) badd = *(const float2*)(g_bpe + (cb - 2) * 128 + colp);
            if (n1 < N)
                *(float2*)(g_P + (size_t)n1 * 512 + col) =
                    make_float2(acc[mt][nt][0] + badd.x, acc[mt][nt][1] + badd.y);
            if (n2 < N)
                *(float2*)(g_P + (size_t)n2 * 512 + col) =
                    make_float2(acc[mt][nt][2] + badd.x, acc[mt][nt][3] + badd.y);
        }
    }
}

// ---------------------------------------------------------------------------
// K5: hidden = relu(P1[from]+P2[to]+ef@Wpe); aggH[to] += hidden (red.v4).
//     Wpe in registers + depth-2 software-pipelined P1/P2 prefetch.
//     128 edges per block (prologue amortized over 32 iterations).
// ---------------------------------------------------------------------------
__global__ void __launch_bounds__(256)
k_hidden(const int* __restrict__ from_idx, const int* __restrict__ to_idx,
         const float* __restrict__ ef, int E) {
    __shared__ __align__(16) float ef_sm[128 * 16];
    __shared__ int from_sm[128], to_sm[128];
    const int tid = threadIdx.x;
    const int e0 = blockIdx.x * 128;
    const int cg = tid & 63, sub = tid >> 6;

    if (tid < 128) {
        int ed = e0 + tid;
        from_sm[tid] = (ed < E) ? from_idx[ed] : -1;
        to_sm[tid]   = (ed < E) ? to_idx[ed] : 0;
    }
#pragma unroll
    for (int i = 0; i < 8; i++) {
        int idx = tid + 256 * i;
        int ed = e0 + (idx >> 4);
        ef_sm[idx] = (ed < E) ? ef[(size_t)ed * 16 + (idx & 15)] : 0.f;
    }
    float4 w[16];
#pragma unroll
    for (int k = 0; k < 16; k++)
        w[k] = *(const float4*)(g_wpe + k * 256 + cg * 4);
    __syncthreads();

    // depth-2 software pipeline: iterations i and i+1 in flight
    int fb[2], tb[2];
    float4 p1b[2], p2b[2];
#pragma unroll
    for (int j = 0; j < 2; j++) {
        fb[j] = from_sm[j * 4 + sub];
        tb[j] = to_sm[j * 4 + sub];
        p1b[j] = make_float4(0.f, 0.f, 0.f, 0.f);
        p2b[j] = p1b[j];
        if (fb[j] >= 0) {
            p1b[j] = *(const float4*)(g_P + (size_t)fb[j] * 512 + cg * 4);
            p2b[j] = *(const float4*)(g_P + (size_t)tb[j] * 512 + 256 + cg * 4);
        }
    }
#pragma unroll 4
    for (int i = 0; i < 32; i++) {
        const int cur = i & 1;
        int f = fb[cur], t = tb[cur];
        float4 p1 = p1b[cur], p2 = p2b[cur];
        if (i + 2 < 32) {
            int fn = from_sm[(i + 2) * 4 + sub];
            int tn = to_sm[(i + 2) * 4 + sub];
            fb[cur] = fn;
            tb[cur] = tn;
            if (fn >= 0) {
                p1b[cur] = *(const float4*)(g_P + (size_t)fn * 512 + cg * 4);
                p2b[cur] = *(const float4*)(g_P + (size_t)tn * 512 + 256 + cg * 4);
            }
        }
        if (f < 0) continue;
        float s0 = p1.x + p2.x, s1 = p1.y + p2.y;
        float s2 = p1.z + p2.z, s3 = p1.w + p2.w;
        const float4* er4 = (const float4*)(ef_sm + (i * 4 + sub) * 16);
#pragma unroll
        for (int k4 = 0; k4 < 4; k4++) {
            float4 ev = er4[k4];
            const float4* wk = w + k4 * 4;
            s0 = fmaf(ev.x, wk[0].x, s0);
            s1 = fmaf(ev.x, wk[0].y, s1);
            s2 = fmaf(ev.x, wk[0].z, s2);
            s3 = fmaf(ev.x, wk[0].w, s3);
            s0 = fmaf(ev.y, wk[1].x, s0);
            s1 = fmaf(ev.y, wk[1].y, s1);
            s2 = fmaf(ev.y, wk[1].z, s2);
            s3 = fmaf(ev.y, wk[1].w, s3);
            s0 = fmaf(ev.z, wk[2].x, s0);
            s1 = fmaf(ev.z, wk[2].y, s1);
            s2 = fmaf(ev.z, wk[2].z, s2);
            s3 = fmaf(ev.z, wk[2].w, s3);
            s0 = fmaf(ev.w, wk[3].x, s0);
            s1 = fmaf(ev.w, wk[3].y, s1);
            s2 = fmaf(ev.w, wk[3].z, s2);
            s3 = fmaf(ev.w, wk[3].w, s3);
        }
        s0 = fmaxf(s0, 0.f); s1 = fmaxf(s1, 0.f);
        s2 = fmaxf(s2, 0.f); s3 = fmaxf(s3, 0.f);
        red4(g_aggH + (size_t)t * 256 + cg * 4, s0, s1, s2, s3);
    }
}

// ---------------------------------------------------------------------------
// K6: node update, 64-row tiles (MT=2) for wave balance.  fp32 h only.
// ---------------------------------------------------------------------------
#define UP_AHI 0
#define UP_ALO 9216
#define UP_BHI 18432
#define UP_BLO 36864
#define UP_END 55296
__global__ void __launch_bounds__(256, 2)
k_upd2(const float* __restrict__ bu, const int* __restrict__ pos, int last,
       int N) {
    extern __shared__ unsigned char sm[];
    const uint32_t base = smem_to_u32(sm);
    const int tid = threadIdx.x, lane = tid & 31, wid = tid >> 5;
    const int n0 = blockIdx.x * 64;
    const int wm = wid >> 2, wn = wid & 3;
    float acc[2][4][4];
#pragma unroll
    for (int i = 0; i < 2; i++)
#pragma unroll
        for (int j = 0; j < 4; j++)
#pragma unroll
            for (int k = 0; k < 4; k++) acc[i][j][k] = 0.f;

    for (int kc = 0; kc < 6; kc++) {
        {
            int row = tid & 127, which = tid >> 7;
            const __nv_bfloat16* src =
                (which ? g_wut2_lo : g_wut2_hi) + (size_t)row * 384 + kc * 64;
            uint32_t dst = base + (which ? UP_BLO : UP_BHI) + row * 144;
#pragma unroll
            for (int j = 0; j < 8; j++) cp_async16(dst + j * 16, src + j * 8);
            CP_COMMIT();
        }
#pragma unroll
        for (int i = 0; i < 4; i++) {
            int idx = tid + 256 * i;
            int row = idx >> 4, q = idx & 15;
            float4 v;
            if (kc < 2)
                v = *(const float4*)(g_h + (size_t)(n0 + row) * 128 +
                                     kc * 64 + q * 4);
            else
                v = *(const float4*)(g_aggH + (size_t)(n0 + row) * 256 +
                                     (kc - 2) * 64 + q * 4);
            __nv_bfloat16 h0 = __float2bfloat16(v.x), h1 = __float2bfloat16(v.y);
            __nv_bfloat16 h2 = __float2bfloat16(v.z), h3 = __float2bfloat16(v.w);
            uint2 hp, lp;
            hp.x = pkbf(v.x, v.y); hp.y = pkbf(v.z, v.w);
            lp.x = pkbf(v.x - __bfloat162float(h0), v.y - __bfloat162float(h1));
            lp.y = pkbf(v.z - __bfloat162float(h2), v.w - __bfloat162float(h3));
            int boff = (row * 72 + q * 4) * 2;
            *(uint2*)(sm + UP_AHI + boff) = hp;
            *(uint2*)(sm + UP_ALO + boff) = lp;
        }
        CP_WAIT0();
        __syncthreads();
#pragma unroll
        for (int p = 0; p < 3; p++) {
            uint32_t aw = base + (p == 1 ? UP_ALO : UP_AHI) + (wm * 32 * 72) * 2;
            uint32_t bw = base + (p == 2 ? UP_BLO : UP_BHI) + (wn * 32) * 144;
            mma_chunk<2, 72, 4>(acc, aw, bw, lane);
        }
        __syncthreads();
    }
#pragma unroll
    for (int mt = 0; mt < 2; mt++) {
        int rr[2];
        rr[0] = wm * 32 + mt * 16 + (lane >> 2);
        rr[1] = rr[0] + 8;
#pragma unroll
        for (int nt = 0; nt < 4; nt++) {
            int col = wn * 32 + nt * 8 + 2 * (lane & 3);
            float2 bb = *(const float2*)(bu + col);
            float2 bc2 = *(const float2*)(g_bc + col);
#pragma unroll
            for (int h = 0; h < 2; h++) {
                int n = n0 + rr[h];
                if (n < N) {
                    float degf = (float)g_deg[n];
                    int pn = 0;
                    if (last) {
                        int slot = pos[n];
                        pn = (slot < 16384)
                                 ? ((slot >> 6) * 128 + (slot & 63))
                                 : (((slot - 16384) >> 6) * 128 + 64 + (slot & 63));
                    }
#pragma unroll
                    for (int z = 0; z < 2; z++) {
                        float v = g_h[(size_t)n * 128 + col + z] +
                                  acc[mt][nt][2 * h + z] + (z ? bb.y : bb.x) +
                                  degf * (z ? bc2.y : bc2.x);
                        if (last)
                            g_flat[(size_t)pn * 128 + col + z] = v;
                        else
                            g_h[(size_t)n * 128 + col + z] = v;
                    }
                }
            }
        }
    }
}

// ---------------------------------------------------------------------------
// K8: fused attention features + pair scoring.
// ---------------------------------------------------------------------------
#define AP_HIDHI 0
#define AP_HIDLO 34816
#define AP_B2HI  73728
#define AP_B2LO  92160
#define AP_BUFA  0
#define AP_BUFB  33024
#define AP_L     66048
#define AP_PC    82688
#define AP_SMEM  110592
__global__ void __launch_bounds__(256, 2)
k_attpair(const float* __restrict__ ba1, const float* __restrict__ ba2,
          const int* __restrict__ qsz, const int* __restrict__ csz,
          float* __restrict__ out) {
    extern __shared__ unsigned char sm[];
    const uint32_t base = smem_to_u32(sm);
    const int tid = threadIdx.x, lane = tid & 31, wid = tid >> 5;
    const int b = blockIdx.x;
    const int r0 = b * 128;
    const int qs = qsz[b], cs = csz[b];
    const int wm = wid >> 2, wn = wid & 3;
    __shared__ float redq[8], redc[8];

    float acc[4][4][4];
#pragma unroll
    for (int i = 0; i < 4; i++)
#pragma unroll
        for (int j = 0; j < 4; j++)
#pragma unroll
            for (int k = 0; k < 4; k++) acc[i][j][k] = 0.f;

    for (int kc = 0; kc < 2; kc++) {
        {
            int row = tid & 127, which = tid >> 7;
            const __nv_bfloat16* src =
                (which ? g_wa1t_lo : g_wa1t_hi) + (size_t)row * 128 + kc * 64;
            uint32_t dst = base + (which ? AP_B2LO : AP_B2HI) + row * 144;
#pragma unroll
            for (int j = 0; j < 8; j++) cp_async16(dst + j * 16, src + j * 8);
            CP_COMMIT();
        }
        build_A_fp32(sm, g_flat, r0, kc * 64, 128, tid);
        CP_WAIT0();
        __syncthreads();
#pragma unroll
        for (int p = 0; p < 3; p++) {
            uint32_t aw = base + (p == 1 ? SL_ALO : SL_AHI) + (wm * 64 * 72) * 2;
            uint32_t bw = base + (p == 2 ? AP_B2LO : AP_B2HI) + (wn * 32) * 144;
            mma_chunk<4, 72, 4>(acc, aw, bw, lane);
        }
        __syncthreads();
    }
#pragma unroll
    for (int mt = 0; mt < 4; mt++) {
        int rr0 = wm * 64 + mt * 16 + (lane >> 2);
#pragma unroll
        for (int nt = 0; nt < 4; nt++) {
            int col = wn * 32 + nt * 8 + 2 * (lane & 3);
            float2 bb = *(const float2*)(ba1 + col);
#pragma unroll
            for (int h = 0; h < 2; h++) {
                int row = rr0 + h * 8;
                float v0 = fmaxf(acc[mt][nt][2 * h]     + bb.x, 0.f);
                float v1 = fmaxf(acc[mt][nt][2 * h + 1] + bb.y, 0.f);
                __nv_bfloat16 b0 = __float2bfloat16(v0), b1 = __float2bfloat16(v1);
                int boff = (row * 136 + col) * 2;
                *(uint32_t*)(sm + AP_HIDHI + boff) = pkbf(v0, v1);
                *(uint32_t*)(sm + AP_HIDLO + boff) =
                    pkbf(v0 - __bfloat162float(b0), v1 - __bfloat162float(b1));
            }
            acc[mt][nt][0] = acc[mt][nt][1] = acc[mt][nt][2] = acc[mt][nt][3] = 0.f;
        }
    }
    __syncthreads();
    for (int kc = 0; kc < 2; kc++) {
        {
            int row = tid & 127, which = tid >> 7;
            const __nv_bfloat16* src =
                (which ? g_wa2t_lo : g_wa2t_hi) + (size_t)row * 128 + kc * 64;
            uint32_t dst = base + (which ? AP_B2LO : AP_B2HI) + row * 144;
#pragma unroll
            for (int j = 0; j < 8; j++) cp_async16(dst + j * 16, src + j * 8);
            CP_COMMIT();
        }
        CP_WAIT0();
        __syncthreads();
#pragma unroll
        for (int p = 0; p < 3; p++) {
            uint32_t aw = base + (p == 1 ? AP_HIDLO : AP_HIDHI) +
                          (wm * 64 * 136 + kc * 64) * 2;
            uint32_t bw = base + (p == 2 ? AP_B2LO : AP_B2HI) + (wn * 32) * 144;
            mma_chunk<4, 136, 4>(acc, aw, bw, lane);
        }
        __syncthreads();
    }
    float* bufA = (float*)(sm + AP_BUFA);
    float* bufB = (float*)(sm + AP_BUFB);
    float* L    = (float*)(sm + AP_L);
    float* pc   = (float*)(sm + AP_PC);
#pragma unroll
    for (int mt = 0; mt < 4; mt++) {
        int rr0 = wm * 64 + mt * 16 + (lane >> 2);
#pragma unroll
        for (int nt = 0; nt < 4; nt++) {
            int col = wn * 32 + nt * 8 + 2 * (lane & 3);
            float2 bb = *(const float2*)(ba2 + col);
#pragma unroll
            for (int h = 0; h < 2; h++) {
                int row = rr0 + h * 8;
                bool isq = row < 64;
                int q = isq ? row : row - 64;
                bool ok = q < (isq ? qs : cs);
                float v0 = ok ? acc[mt][nt][2 * h]     + bb.x : 0.f;
                float v1 = ok ? acc[mt][nt][2 * h + 1] + bb.y : 0.f;
                float* dst = isq ? bufA : bufB;
                dst[q * 129 + col]     = v0;
                dst[q * 129 + col + 1] = v1;
            }
        }
    }
    __syncthreads();
    {
        int q = tid >> 2, cg = tid & 3;
        float la[16];
#pragma unroll
        for (int j = 0; j < 16; j++) la[j] = 0.f;
        for (int k = 0; k < 128; k++) {
            float a = bufA[q * 129 + k];
            const float* bp = bufB + (cg * 16) * 129 + k;
#pragma unroll
            for (int j = 0; j < 16; j++) la[j] += a * bp[j * 129];
        }
        bool qv = q < qs;
#pragma unroll
        for (int j = 0; j < 16; j++) {
            int c = cg * 16 + j;
            L[q * 65 + c] = (qv && c < cs) ? la[j] * 10.0f : -1e9f;
        }
    }
    __syncthreads();
    for (int idx = tid; idx < 64 * 128; idx += 256) {
        int r = idx >> 7, k = idx & 127;
        bufA[r * 129 + k] = g_flat[(size_t)(r0 + r) * 128 + k];
        bufB[r * 129 + k] = g_flat[(size_t)(r0 + 64 + r) * 128 + k];
    }
    if (tid < 64) {
        int c = tid;
        float m = -1e30f;
        for (int q = 0; q < 64; q++) m = fmaxf(m, L[q * 65 + c]);
        float s = 0.f;
        for (int q = 0; q < 64; q++) {
            float ex = __expf(L[q * 65 + c] - m);
            s += ex;
            pc[q * 65 + c] = ex;
        }
        float inv = (c < cs) ? (1.0f / s) : 0.f;
        for (int q = 0; q < 64; q++) pc[q * 65 + c] *= inv;
    }
    __syncthreads();
    if (tid < 64) {
        float m = -1e30f;
        for (int c = 0; c < 64; c++) m = fmaxf(m, L[tid * 65 + c]);
        float s = 0.f;
        for (int c = 0; c < 64; c++) {
            float ex = __expf(L[tid * 65 + c] - m);
            s += ex;
            L[tid * 65 + c] = ex;
        }
        float inv = (tid < qs) ? (1.0f / s) : 0.f;
        for (int c = 0; c < 64; c++) L[tid * 65 + c] *= inv;
    }
    __syncthreads();
    float lq = 0.f, lc = 0.f;
    {
        const int d = tid & 127, gg = tid >> 7;
        float av[32];
#pragma unroll
        for (int j = 0; j < 32; j++) av[j] = 0.f;
        for (int c = 0; c < 64; c++) {
            float bb = bufB[c * 129 + d];
            const float* pp = L + (gg * 32) * 65 + c;
#pragma unroll
            for (int j = 0; j < 32; j++) av[j] += pp[j * 65] * bb;
        }
#pragma unroll
        for (int j = 0; j < 32; j++) {
            int q = gg * 32 + j;
            lq += fmaxf(bufA[q * 129 + d] - av[j], 0.f);
        }
#pragma unroll
        for (int j = 0; j < 32; j++) av[j] = 0.f;
        for (int q = 0; q < 64; q++) {
            float aa = bufA[q * 129 + d];
            const float* pp = pc + q * 65 + gg * 32;
#pragma unroll
            for (int j = 0; j < 32; j++) av[j] += pp[j] * aa;
        }
#pragma unroll
        for (int j = 0; j < 32; j++) {
            int c = gg * 32 + j;
            lc += fmaxf(bufB[c * 129 + d] - av[j], 0.f);
        }
    }
    for (int o = 16; o; o >>= 1) {
        lq += __shfl_down_sync(0xffffffffu, lq, o);
        lc += __shfl_down_sync(0xffffffffu, lc, o);
    }
    if (lane == 0) { redq[wid] = lq; redc[wid] = lc; }
    __syncthreads();
    if (tid == 0) {
        float sq = 0.f, sc = 0.f;
        for (int i = 0; i < 8; i++) { sq += redq[i]; sc += redc[i]; }
        out[b] = fminf(-sq, -sc);
    }
}

// ---------------------------------------------------------------------------
extern "C" void kernel_launch(void* const* d_in, const int* in_sizes, int n_in,
                              void* d_out, int out_size) {
    const float* nf       = (const float*)d_in[0];
    const float* ef       = (const float*)d_in[1];
    const int*   from_idx = (const int*)d_in[2];
    const int*   to_idx   = (const int*)d_in[3];
    const int*   pos      = (const int*)d_in[4];
    const int*   qsz      = (const int*)d_in[5];
    const int*   csz      = (const int*)d_in[6];
    const float* W_node = (const float*)d_in[7];
    const float* b_node = (const float*)d_in[8];
    const float* W_edge = (const float*)d_in[9];
    const float* b_edge = (const float*)d_in[10];
    const float* W_msg1 = (const float*)d_in[11];
    const float* b_msg1 = (const float*)d_in[12];
    const float* W_msg2 = (const float*)d_in[13];
    const float* b_msg2 = (const float*)d_in[14];
    const float* W_upd  = (const float*)d_in[15];
    const float* b_upd  = (const float*)d_in[16];
    const float* Wa1    = (const float*)d_in[17];
    const float* ba1    = (const float*)d_in[18];
    const float* Wa2    = (const float*)d_in[19];
    const float* ba2    = (const float*)d_in[20];

    const int N = in_sizes[0] / 32;
    const int E = in_sizes[1] / 16;

    cudaFuncSetAttribute(k_nodeprod, cudaFuncAttributeMaxDynamicSharedMemorySize, SL_END);
    cudaFuncSetAttribute(k_upd2,     cudaFuncAttributeMaxDynamicSharedMemorySize, UP_END);
    cudaFuncSetAttribute(k_attpair,  cudaFuncAttributeMaxDynamicSharedMemorySize, AP_SMEM);

    const int egrid   = (E + 127) / 128;
    const int ngrid   = (N + 127) / 128;
    const int ngrid64 = (N + 63) / 64;
    const int degz    = (N + 255) / 256;
    const int encg    = (N + 15) / 16;

    k_setup1<<<528 + degz + encg, 256>>>(W_msg1, Wa1, Wa2, W_msg2, W_upd,
                                         W_edge, nf, W_node, b_node, degz, N);
    k_setup2<<<194 + (E + 255) / 256, 256>>>(W_upd, b_msg2, W_msg1, b_msg1,
                                             b_edge, to_idx, E);

    for (int s = 0; s < 3; s++) {
        k_nodeprod<<<ngrid * 4, 256, SL_END>>>(N);
        k_hidden<<<egrid, 256>>>(from_idx, to_idx, ef, E);
        k_upd2<<<ngrid64, 256, UP_END>>>(b_upd, pos, s == 2 ? 1 : 0, N);
    }

    k_attpair<<<256, 256, AP_SMEM>>>(ba1, ba2, qsz, csz, (float*)d_out);
}